// round 1
// baseline (speedup 1.0000x reference)
#include <cuda_runtime.h>
#include <math.h>

// ---------------------------------------------------------------------------
// GodAreaModel: 4 areas x 2048 neurons, batch 512, 4 ticks.
// Outputs: logits [512,1024] then history [5,4,512,2048], fp32.
// ---------------------------------------------------------------------------

#define A_NUM   4
#define AREA_N  2048
#define NTOT    8192           // A_NUM * AREA_N
#define D_INPUT 1024
#define NCLS    1024
#define BATCH   512
#define NTICKS  4
#define THRESH  0.05f

#define LOGITS_ELEMS (BATCH * NCLS)
#define HIST_STEP    (A_NUM * BATCH * AREA_N)   // one history timestep

// ------------------------- device scratch (static) -------------------------
__device__ __align__(256) float g_Weff[(size_t)NTOT * NTOT];   // 256 MiB
__device__ __align__(256) float g_Owg [(size_t)NCLS * NTOT];   // 32 MiB
__device__ __align__(256) float g_Z0  [(size_t)BATCH * NTOT];  // 16 MiB
__device__ __align__(256) float g_Z1  [(size_t)BATCH * NTOT];  // 16 MiB
__device__ __align__(256) float g_partials[A_NUM * 64];
__device__ __align__(256) float g_gatev[A_NUM];
__device__ __align__(256) float g_biasv[NTOT];

// ------------------------- prep kernels -------------------------

// Weff[p, q] = W_blocks[o,i,n,m] * clamp(mask, 0, 1), p = o*2048+n, q = i*2048+m
__global__ void prep_weff_kernel(const float* __restrict__ W,
                                 const float* __restrict__ mask) {
    size_t idx = (size_t)blockIdx.x * blockDim.x + threadIdx.x;
    int p = (int)(idx >> 13);
    int q = (int)(idx & 8191);
    int o = p >> 11, n = p & 2047;
    int i = q >> 11, m = q & 2047;
    size_t src = ((size_t)((o * A_NUM + i) * AREA_N + n)) * AREA_N + m;
    float mk = fminf(fmaxf(mask[src], 0.0f), 1.0f);
    g_Weff[idx] = W[src] * mk;
}

// Owg[c, k] = Ow[c, area_idx_flat[k]]  (permutation gather of classifier cols)
__global__ void prep_owg_kernel(const float* __restrict__ Ow,
                                const int* __restrict__ aidx) {
    int idx = blockIdx.x * blockDim.x + threadIdx.x;
    int c = idx >> 13, k = idx & 8191;
    g_Owg[(size_t)idx] = Ow[(size_t)c * NTOT + aidx[k]];
}

// ------------------------- gate reductions (deterministic) -------------------------

// grid (64, A_NUM): block (blk, area) sums |Z| over rows blk*8..blk*8+7,
// cols [area*2048, area*2048+2048). Fixed-order tree reduce -> g_partials.
__global__ void reduce_absmean_kernel(const float* __restrict__ Z) {
    int area = blockIdx.y;
    int blk  = blockIdx.x;
    float s = 0.0f;
    #pragma unroll
    for (int r = 0; r < 8; r++) {
        int b = blk * 8 + r;
        const float* row = Z + (size_t)b * NTOT + area * AREA_N;
        for (int c = threadIdx.x; c < AREA_N; c += 256) s += fabsf(row[c]);
    }
    __shared__ float sm[256];
    sm[threadIdx.x] = s;
    __syncthreads();
    for (int st = 128; st > 0; st >>= 1) {
        if (threadIdx.x < st) sm[threadIdx.x] += sm[threadIdx.x + st];
        __syncthreads();
    }
    if (threadIdx.x == 0) g_partials[area * 64 + blk] = sm[0];
}

// one block: finalize gates, then bias_t[p] = sum_i gate[i]*b_blocks[o,i,n]
__global__ void gate_bias_kernel(const float* __restrict__ b_blocks) {
    __shared__ float gsh[A_NUM];
    if (threadIdx.x < A_NUM) {
        float s = 0.0f;
        for (int j = 0; j < 64; j++) s += g_partials[threadIdx.x * 64 + j];
        float mean = s / (float)((size_t)BATCH * AREA_N);
        float g = (mean > THRESH) ? 1.0f : 0.0f;
        g_gatev[threadIdx.x] = g;
        gsh[threadIdx.x] = g;
    }
    __syncthreads();
    for (int p = threadIdx.x; p < NTOT; p += 256) {
        int o = p >> 11, n = p & 2047;
        float s = 0.0f;
        #pragma unroll
        for (int i = 0; i < A_NUM; i++)
            s += gsh[i] * b_blocks[(o * A_NUM + i) * AREA_N + n];
        g_biasv[p] = s;
    }
}

// ------------------------- fused NT GEMM -------------------------
// C[m,n] = sum_k A[m,k] * B[n,k]   (A: [M,K] row-major, B: [N,K] row-major)
// gate != null: skip K-blocks whose area gate == 0 (gate is exactly 0/1)
// epilogue: + bias[n], optional tanh, write Cout[m*N+n] and history slice.
#define BM 128
#define BN 128
#define BK 16
#define TM 8
#define TN 8

__global__ __launch_bounds__(256, 2)
void gemm_nt_kernel(const float* __restrict__ A, const float* __restrict__ Bm,
                    int M, int N, int K,
                    const float* __restrict__ gate,
                    const float* __restrict__ bias,
                    int do_tanh,
                    float* __restrict__ Cout,
                    float* __restrict__ hist) {
    __shared__ float As[BK][BM];
    __shared__ float Bs[BK][BN];
    __shared__ float gsm[A_NUM];

    int tid = threadIdx.x;
    int m0 = blockIdx.y * BM;
    int n0 = blockIdx.x * BN;
    int tx = tid & 15, ty = tid >> 4;

    if (tid < A_NUM) gsm[tid] = gate ? gate[tid] : 1.0f;
    __syncthreads();

    float acc[TM][TN];
    #pragma unroll
    for (int i = 0; i < TM; i++)
        #pragma unroll
        for (int j = 0; j < TN; j++) acc[i][j] = 0.0f;

    for (int k0 = 0; k0 < K; k0 += BK) {
        if (gate && gsm[k0 >> 11] == 0.0f) continue;  // uniform branch

        // load A tile [BM x BK] -> As[k][m]; 512 float4, 2 per thread
        #pragma unroll
        for (int r = 0; r < 2; r++) {
            int f = tid + r * 256;
            int row = f >> 2;        // 0..127
            int kq  = f & 3;         // float4 within BK
            float4 v = *(const float4*)(A + (size_t)(m0 + row) * K + k0 + kq * 4);
            As[kq * 4 + 0][row] = v.x;
            As[kq * 4 + 1][row] = v.y;
            As[kq * 4 + 2][row] = v.z;
            As[kq * 4 + 3][row] = v.w;
        }
        // load B tile [BN x BK] -> Bs[k][n]
        #pragma unroll
        for (int r = 0; r < 2; r++) {
            int f = tid + r * 256;
            int row = f >> 2;
            int kq  = f & 3;
            float4 v = *(const float4*)(Bm + (size_t)(n0 + row) * K + k0 + kq * 4);
            Bs[kq * 4 + 0][row] = v.x;
            Bs[kq * 4 + 1][row] = v.y;
            Bs[kq * 4 + 2][row] = v.z;
            Bs[kq * 4 + 3][row] = v.w;
        }
        __syncthreads();

        #pragma unroll
        for (int kk = 0; kk < BK; kk++) {
            float4 a0 = *(const float4*)&As[kk][ty * TM];
            float4 a1 = *(const float4*)&As[kk][ty * TM + 4];
            float4 b0 = *(const float4*)&Bs[kk][tx * TN];
            float4 b1 = *(const float4*)&Bs[kk][tx * TN + 4];
            float ra[TM] = {a0.x, a0.y, a0.z, a0.w, a1.x, a1.y, a1.z, a1.w};
            float rbv[TN] = {b0.x, b0.y, b0.z, b0.w, b1.x, b1.y, b1.z, b1.w};
            #pragma unroll
            for (int i = 0; i < TM; i++)
                #pragma unroll
                for (int j = 0; j < TN; j++)
                    acc[i][j] += ra[i] * rbv[j];
        }
        __syncthreads();
    }

    // epilogue
    #pragma unroll
    for (int i = 0; i < TM; i++) {
        int m = m0 + ty * TM + i;
        #pragma unroll
        for (int j = 0; j < TN; j++) {
            int n = n0 + tx * TN + j;
            float v = acc[i][j];
            if (bias) v += bias[n];
            if (do_tanh) v = tanhf(v);
            Cout[(size_t)m * N + n] = v;
            if (hist) {
                int a  = n >> 11;
                int nn = n & 2047;
                hist[((size_t)a * BATCH + m) * AREA_N + nn] = v;
            }
        }
    }
}

// ------------------------- launch -------------------------
extern "C" void kernel_launch(void* const* d_in, const int* in_sizes, int n_in,
                              void* d_out, int out_size) {
    const float* x    = (const float*)d_in[0];
    const float* Rw   = (const float*)d_in[1];
    const float* rb   = (const float*)d_in[2];
    const float* Wb   = (const float*)d_in[3];
    const float* bb   = (const float*)d_in[4];
    const float* mask = (const float*)d_in[5];
    const float* Ow   = (const float*)d_in[6];
    const float* Ob   = (const float*)d_in[7];
    const int*   aidx = (const int*)d_in[8];

    float* out  = (float*)d_out;
    float* hist = out + LOGITS_ELEMS;

    float *zA, *zB, *weff, *owg, *gatev, *biasv;
    cudaGetSymbolAddress((void**)&zA,    g_Z0);
    cudaGetSymbolAddress((void**)&zB,    g_Z1);
    cudaGetSymbolAddress((void**)&weff,  g_Weff);
    cudaGetSymbolAddress((void**)&owg,   g_Owg);
    cudaGetSymbolAddress((void**)&gatev, g_gatev);
    cudaGetSymbolAddress((void**)&biasv, g_biasv);

    // 1) precompute masked weights + permuted classifier
    prep_weff_kernel<<<(unsigned)(((size_t)NTOT * NTOT) / 256), 256>>>(Wb, mask);
    prep_owg_kernel<<<(NCLS * NTOT) / 256, 256>>>(Ow, aidx);

    // 2) encode: Z0 = tanh(x @ Rw^T + rb); also writes history[0]
    gemm_nt_kernel<<<dim3(NTOT / BN, BATCH / BM), 256>>>(
        x, Rw, BATCH, NTOT, D_INPUT, nullptr, rb, 1, zA, hist);

    // 3) ticks
    float* cur = zA;
    float* nxt = zB;
    for (int t = 0; t < NTICKS; t++) {
        reduce_absmean_kernel<<<dim3(64, A_NUM), 256>>>(cur);
        gate_bias_kernel<<<1, 256>>>(bb);
        gemm_nt_kernel<<<dim3(NTOT / BN, BATCH / BM), 256>>>(
            cur, weff, BATCH, NTOT, NTOT, gatev, biasv, 1, nxt,
            hist + (size_t)(t + 1) * HIST_STEP);
        float* tmp = cur; cur = nxt; nxt = tmp;
    }

    // 4) logits = Z @ Owg^T + Ob
    gemm_nt_kernel<<<dim3(NCLS / BN, BATCH / BM), 256>>>(
        cur, owg, BATCH, NCLS, NTOT, nullptr, Ob, 0, out, nullptr);
}

// round 3
// speedup vs baseline: 1.5004x; 1.5004x over previous
#include <cuda_runtime.h>
#include <cuda_bf16.h>
#include <math.h>
#include <stdint.h>

// ---------------------------------------------------------------------------
// GodAreaModel via mma.sync bf16 (3-term split => fp32 accuracy).
// Baseline PTX only (no 'a'-gated instructions).
// ---------------------------------------------------------------------------

#define A_NUM   4
#define AREA_N  2048
#define NTOT    8192
#define D_INPUT 1024
#define NCLS    1024
#define BATCH   512
#define NTICKS  4
#define THRESH  0.05f
#define LOGITS_ELEMS (BATCH * NCLS)
#define HIST_STEP    (A_NUM * BATCH * AREA_N)

// Block tile
#define BM 128
#define BN 128
#define BK 32
#define TILE_BYTES (BM * BK * 2)            // 8192 per operand tile
#define STAGE_BYTES (4 * TILE_BYTES)        // Ahi,Alo,Bhi,Blo = 32KB
#define SMEM_DYN (2 * STAGE_BYTES)          // 64KB

// ------------------------- device scratch -------------------------
__device__ __align__(256) __nv_bfloat16 g_Whi[(size_t)NTOT * NTOT];
__device__ __align__(256) __nv_bfloat16 g_Wlo[(size_t)NTOT * NTOT];
__device__ __align__(256) __nv_bfloat16 g_Rhi[(size_t)NTOT * D_INPUT];
__device__ __align__(256) __nv_bfloat16 g_Rlo[(size_t)NTOT * D_INPUT];
__device__ __align__(256) __nv_bfloat16 g_Ohi[(size_t)NCLS * NTOT];
__device__ __align__(256) __nv_bfloat16 g_Olo[(size_t)NCLS * NTOT];
__device__ __align__(256) __nv_bfloat16 g_xhi[(size_t)BATCH * D_INPUT];
__device__ __align__(256) __nv_bfloat16 g_xlo[(size_t)BATCH * D_INPUT];
__device__ __align__(256) __nv_bfloat16 g_Zhi0[(size_t)BATCH * NTOT];
__device__ __align__(256) __nv_bfloat16 g_Zlo0[(size_t)BATCH * NTOT];
__device__ __align__(256) __nv_bfloat16 g_Zhi1[(size_t)BATCH * NTOT];
__device__ __align__(256) __nv_bfloat16 g_Zlo1[(size_t)BATCH * NTOT];
__device__ __align__(256) float g_tsum[256];
__device__ __align__(256) float g_gatev[A_NUM];
__device__ __align__(256) float g_biasv[NTOT];

// ------------------------- helpers -------------------------
__device__ __forceinline__ uint32_t smem_u32(const void* p) {
    return (uint32_t)__cvta_generic_to_shared(p);
}
__device__ __forceinline__ uint32_t pack2(__nv_bfloat16 a, __nv_bfloat16 b) {
    __nv_bfloat162 v; v.x = a; v.y = b;
    return *reinterpret_cast<uint32_t*>(&v);
}
__device__ __forceinline__ void split_bf16(float w, __nv_bfloat16& h, __nv_bfloat16& l) {
    h = __float2bfloat16(w);
    l = __float2bfloat16(w - __bfloat162float(h));
}
__device__ __forceinline__ void cp16(uint32_t saddr, const void* g) {
    asm volatile("cp.async.cg.shared.global [%0], [%1], 16;" :: "r"(saddr), "l"(g));
}
// swizzled byte offset within a 128x32 bf16 tile (rows of 64B, 16B chunks)
__device__ __forceinline__ uint32_t swz(uint32_t row, uint32_t chunk) {
    return row * 64u + ((chunk ^ ((row >> 1) & 3u)) << 4);
}
__device__ __forceinline__ void ldsm4(uint32_t addr, uint32_t* r) {
    asm volatile("ldmatrix.sync.aligned.m8n8.x4.shared.b16 {%0,%1,%2,%3}, [%4];"
                 : "=r"(r[0]), "=r"(r[1]), "=r"(r[2]), "=r"(r[3]) : "r"(addr));
}
__device__ __forceinline__ void mma16816(float* c, const uint32_t* a, const uint32_t* b) {
    asm volatile(
        "mma.sync.aligned.m16n8k16.row.col.f32.bf16.bf16.f32 "
        "{%0,%1,%2,%3}, {%4,%5,%6,%7}, {%8,%9}, {%0,%1,%2,%3};"
        : "+f"(c[0]), "+f"(c[1]), "+f"(c[2]), "+f"(c[3])
        : "r"(a[0]), "r"(a[1]), "r"(a[2]), "r"(a[3]), "r"(b[0]), "r"(b[1]));
}

// ------------------------- prep kernels -------------------------
// Weff split, row-major [n=o*2048+nn][k=i*2048+mm]
__global__ void prep_wsplit(const float* __restrict__ W, const float* __restrict__ mask) {
    size_t t = (size_t)blockIdx.x * blockDim.x + threadIdx.x;
    size_t s = t * 2;
    float2 w  = *(const float2*)(W + s);
    float2 mk = *(const float2*)(mask + s);
    float w0 = w.x * fminf(fmaxf(mk.x, 0.f), 1.f);
    float w1 = w.y * fminf(fmaxf(mk.y, 0.f), 1.f);
    int m = (int)(s & 2047);
    size_t r = s >> 11;
    int n = (int)(r & 2047); r >>= 11;
    int i = (int)(r & 3);
    int o = (int)(r >> 2);
    size_t dst = ((size_t)((o << 11) | n)) * NTOT + ((i << 11) | m);
    __nv_bfloat16 h0, l0, h1, l1;
    split_bf16(w0, h0, l0); split_bf16(w1, h1, l1);
    *(uint32_t*)(g_Whi + dst) = pack2(h0, h1);
    *(uint32_t*)(g_Wlo + dst) = pack2(l0, l1);
}
// Rw flat [8192][1024] (already contiguous)
__global__ void prep_rsplit(const float* __restrict__ Rw) {
    size_t s = ((size_t)blockIdx.x * blockDim.x + threadIdx.x) * 2;
    float2 w = *(const float2*)(Rw + s);
    __nv_bfloat16 h0, l0, h1, l1;
    split_bf16(w.x, h0, l0); split_bf16(w.y, h1, l1);
    *(uint32_t*)(g_Rhi + s) = pack2(h0, h1);
    *(uint32_t*)(g_Rlo + s) = pack2(l0, l1);
}
// Ow gathered: Ohi[c][k] = Ow[c][aidx[k]]
__global__ void prep_osplit(const float* __restrict__ Ow, const int* __restrict__ aidx) {
    size_t s = ((size_t)blockIdx.x * blockDim.x + threadIdx.x) * 2;
    int k = (int)(s & 8191);
    int c = (int)(s >> 13);
    float w0 = Ow[(size_t)c * NTOT + aidx[k]];
    float w1 = Ow[(size_t)c * NTOT + aidx[k + 1]];
    __nv_bfloat16 h0, l0, h1, l1;
    split_bf16(w0, h0, l0); split_bf16(w1, h1, l1);
    *(uint32_t*)(g_Ohi + s) = pack2(h0, h1);
    *(uint32_t*)(g_Olo + s) = pack2(l0, l1);
}
__global__ void prep_xsplit(const float* __restrict__ x) {
    size_t s = ((size_t)blockIdx.x * blockDim.x + threadIdx.x) * 2;
    float2 w = *(const float2*)(x + s);
    __nv_bfloat16 h0, l0, h1, l1;
    split_bf16(w.x, h0, l0); split_bf16(w.y, h1, l1);
    *(uint32_t*)(g_xhi + s) = pack2(h0, h1);
    *(uint32_t*)(g_xlo + s) = pack2(l0, l1);
}
// gates + gated bias (tsum layout: [mtile(4)][ntile(64)])
__global__ void gate_bias_kernel(const float* __restrict__ bb) {
    __shared__ float gsh[A_NUM];
    int t = threadIdx.x;
    if (t < A_NUM) {
        float s = 0.0f;
        for (int mt = 0; mt < 4; mt++)
            for (int nt = t * 16; nt < t * 16 + 16; nt++)
                s += g_tsum[mt * 64 + nt];
        float mean = s * (1.0f / (float)(BATCH * AREA_N));
        float g = (mean > THRESH) ? 1.0f : 0.0f;
        g_gatev[t] = g;
        gsh[t] = g;
    }
    __syncthreads();
    for (int p = t; p < NTOT; p += 256) {
        int o = p >> 11, n = p & 2047;
        float s = 0.0f;
        #pragma unroll
        for (int i = 0; i < A_NUM; i++)
            s += gsh[i] * bb[(o * A_NUM + i) * AREA_N + n];
        g_biasv[p] = s;
    }
}

// ------------------------- stage loader -------------------------
__device__ __forceinline__ void load_tile(uint32_t sb, const __nv_bfloat16* g, int ld, int tid) {
    #pragma unroll
    for (int r = 0; r < 2; r++) {
        int id = tid + r * 256;
        uint32_t row = (uint32_t)id >> 2, c = (uint32_t)id & 3;
        cp16(sb + swz(row, c), g + (size_t)row * ld + c * 8);
    }
}
__device__ __forceinline__ void load_stage(
    uint32_t sb,
    const __nv_bfloat16* Ahi, const __nv_bfloat16* Alo,
    const __nv_bfloat16* Bhi, const __nv_bfloat16* Blo,
    int m0, int n0, int k0, int K, int tid)
{
    load_tile(sb,                  Ahi + (size_t)m0 * K + k0, K, tid);
    load_tile(sb + TILE_BYTES,     Alo + (size_t)m0 * K + k0, K, tid);
    load_tile(sb + 2 * TILE_BYTES, Bhi + (size_t)n0 * K + k0, K, tid);
    load_tile(sb + 3 * TILE_BYTES, Blo + (size_t)n0 * K + k0, K, tid);
    asm volatile("cp.async.commit_group;" ::: "memory");
}

// ------------------------- main GEMM -------------------------
// C[m,n] = sum_k A[m,k]*B[n,k], 3x bf16 split, fp32 reg accumulators.
__global__ __launch_bounds__(256, 1)
void god_gemm(const __nv_bfloat16* __restrict__ Ahi, const __nv_bfloat16* __restrict__ Alo,
              const __nv_bfloat16* __restrict__ Bhi, const __nv_bfloat16* __restrict__ Blo,
              int K,
              const float* __restrict__ gate,
              const float* __restrict__ bias,
              float* __restrict__ hist,
              float* __restrict__ logits, int logitsN,
              __nv_bfloat16* __restrict__ Zho, __nv_bfloat16* __restrict__ Zlo_out,
              float* __restrict__ tsum,
              int do_tanh)
{
    extern __shared__ char dsm[];
    __shared__ short s_act[256];
    __shared__ int s_nact;
    __shared__ float s_wsum[8];

    const int tid  = threadIdx.x;
    const int wid  = tid >> 5, lane = tid & 31;
    const int wm   = wid >> 2;          // 0..1 -> 64-row slab
    const int wn   = wid & 3;           // 0..3 -> 32-col slab
    const int m0   = blockIdx.y * BM;
    const int n0   = blockIdx.x * BN;
    const uint32_t sbase = smem_u32(dsm);

    if (tid == 0) {
        int ktiles = K / BK;
        int n = 0;
        for (int kt = 0; kt < ktiles; kt++)
            if (!gate || gate[kt >> 6] != 0.0f) s_act[n++] = (short)kt;
        s_nact = n;
    }
    __syncthreads();
    const int nact = s_nact;

    float acc[4][4][4];
    #pragma unroll
    for (int a = 0; a < 4; a++)
        #pragma unroll
        for (int b = 0; b < 4; b++)
            #pragma unroll
            for (int c = 0; c < 4; c++) acc[a][b][c] = 0.0f;

    // per-lane ldmatrix address components
    const uint32_t a_row = (lane & 7) + ((lane >> 3) & 1) * 8;  // row within 16
    const uint32_t a_ch  = (lane >> 4);                         // 0/1 k-chunk
    const uint32_t b_row = (lane & 7) + (lane >> 4) * 8;
    const uint32_t b_ch  = (lane >> 3) & 1;

    if (nact > 0)
        load_stage(sbase, Ahi, Alo, Bhi, Blo, m0, n0, s_act[0] * BK, K, tid);

    #pragma unroll 1
    for (int i = 0; i < nact; i++) {
        const uint32_t sb = sbase + (uint32_t)(i & 1) * STAGE_BYTES;
        if (i + 1 < nact) {
            load_stage(sbase + (uint32_t)((i + 1) & 1) * STAGE_BYTES,
                       Ahi, Alo, Bhi, Blo, m0, n0, s_act[i + 1] * BK, K, tid);
            asm volatile("cp.async.wait_group 1;" ::: "memory");
        } else {
            asm volatile("cp.async.wait_group 0;" ::: "memory");
        }
        __syncthreads();

        const uint32_t sA = sb;
        const uint32_t sAl = sb + TILE_BYTES;
        const uint32_t sB = sb + 2 * TILE_BYTES;
        const uint32_t sBl = sb + 3 * TILE_BYTES;

        #pragma unroll
        for (int ks = 0; ks < 2; ks++) {
            uint32_t ah[4][4], al[4][4];
            #pragma unroll
            for (int mt = 0; mt < 4; mt++) {
                uint32_t row = wm * 64 + mt * 16 + a_row;
                uint32_t off = swz(row, ks * 2 + a_ch);
                ldsm4(sA + off, ah[mt]);
                ldsm4(sAl + off, al[mt]);
            }
            uint32_t bh[2][4], bl[2][4];
            #pragma unroll
            for (int ng = 0; ng < 2; ng++) {
                uint32_t row = wn * 32 + ng * 16 + b_row;
                uint32_t off = swz(row, ks * 2 + b_ch);
                ldsm4(sB + off, bh[ng]);
                ldsm4(sBl + off, bl[ng]);
            }
            #pragma unroll
            for (int mt = 0; mt < 4; mt++)
                #pragma unroll
                for (int nt = 0; nt < 4; nt++) {
                    const uint32_t* bph = bh[nt >> 1] + (nt & 1) * 2;
                    const uint32_t* bpl = bl[nt >> 1] + (nt & 1) * 2;
                    mma16816(acc[mt][nt], ah[mt], bph);
                    mma16816(acc[mt][nt], al[mt], bph);
                    mma16816(acc[mt][nt], ah[mt], bpl);
                }
        }
        __syncthreads();
    }

    // ---- epilogue ----
    float asum = 0.0f;
    const int lrow = lane >> 2;        // 0..7
    const int lcol = (lane & 3) * 2;   // even col
    #pragma unroll
    for (int mt = 0; mt < 4; mt++) {
        #pragma unroll
        for (int half = 0; half < 2; half++) {
            const int m = m0 + wm * 64 + mt * 16 + lrow + half * 8;
            #pragma unroll
            for (int nt = 0; nt < 4; nt++) {
                const int n = n0 + wn * 32 + nt * 8 + lcol;
                float v0 = acc[mt][nt][half * 2 + 0] + (bias ? __ldg(bias + n) : 0.0f);
                float v1 = acc[mt][nt][half * 2 + 1] + (bias ? __ldg(bias + n + 1) : 0.0f);
                if (do_tanh) { v0 = tanhf(v0); v1 = tanhf(v1); }
                asum += fabsf(v0) + fabsf(v1);
                if (hist) {
                    int a = n >> 11, nn = n & 2047;
                    *(float2*)(hist + ((size_t)a * BATCH + m) * AREA_N + nn) =
                        make_float2(v0, v1);
                }
                if (logits)
                    *(float2*)(logits + (size_t)m * logitsN + n) = make_float2(v0, v1);
                if (Zho) {
                    __nv_bfloat16 h0, l0, h1, l1;
                    split_bf16(v0, h0, l0); split_bf16(v1, h1, l1);
                    *(uint32_t*)(Zho     + (size_t)m * NTOT + n) = pack2(h0, h1);
                    *(uint32_t*)(Zlo_out + (size_t)m * NTOT + n) = pack2(l0, l1);
                }
            }
        }
    }

    if (tsum) {
        #pragma unroll
        for (int o = 16; o; o >>= 1) asum += __shfl_xor_sync(0xffffffffu, asum, o);
        if (lane == 0) s_wsum[wid] = asum;
        __syncthreads();
        if (tid == 0) {
            float s = ((s_wsum[0] + s_wsum[1]) + (s_wsum[2] + s_wsum[3]))
                    + ((s_wsum[4] + s_wsum[5]) + (s_wsum[6] + s_wsum[7]));
            tsum[blockIdx.y * 64 + blockIdx.x] = s;
        }
    }
}

// ------------------------- launch -------------------------
extern "C" void kernel_launch(void* const* d_in, const int* in_sizes, int n_in,
                              void* d_out, int out_size) {
    const float* x    = (const float*)d_in[0];
    const float* Rw   = (const float*)d_in[1];
    const float* rb   = (const float*)d_in[2];
    const float* Wb   = (const float*)d_in[3];
    const float* bb   = (const float*)d_in[4];
    const float* mask = (const float*)d_in[5];
    const float* Ow   = (const float*)d_in[6];
    const float* Ob   = (const float*)d_in[7];
    const int*   aidx = (const int*)d_in[8];

    float* out  = (float*)d_out;
    float* hist = out + LOGITS_ELEMS;

    __nv_bfloat16 *whi, *wlo, *rhi, *rlo, *ohi, *olo, *xhi, *xlo;
    __nv_bfloat16 *zhi[2], *zlo[2];
    float *tsum, *gatev, *biasv;
    cudaGetSymbolAddress((void**)&whi, g_Whi);
    cudaGetSymbolAddress((void**)&wlo, g_Wlo);
    cudaGetSymbolAddress((void**)&rhi, g_Rhi);
    cudaGetSymbolAddress((void**)&rlo, g_Rlo);
    cudaGetSymbolAddress((void**)&ohi, g_Ohi);
    cudaGetSymbolAddress((void**)&olo, g_Olo);
    cudaGetSymbolAddress((void**)&xhi, g_xhi);
    cudaGetSymbolAddress((void**)&xlo, g_xlo);
    cudaGetSymbolAddress((void**)&zhi[0], g_Zhi0);
    cudaGetSymbolAddress((void**)&zlo[0], g_Zlo0);
    cudaGetSymbolAddress((void**)&zhi[1], g_Zhi1);
    cudaGetSymbolAddress((void**)&zlo[1], g_Zlo1);
    cudaGetSymbolAddress((void**)&tsum,  g_tsum);
    cudaGetSymbolAddress((void**)&gatev, g_gatev);
    cudaGetSymbolAddress((void**)&biasv, g_biasv);

    cudaFuncSetAttribute(god_gemm, cudaFuncAttributeMaxDynamicSharedMemorySize, SMEM_DYN);

    // 1) split/prep
    prep_wsplit<<<131072, 256>>>(Wb, mask);
    prep_rsplit<<<16384, 256>>>(Rw);
    prep_osplit<<<16384, 256>>>(Ow, aidx);
    prep_xsplit<<<1024, 256>>>(x);

    // 2) encode (K=1024): Z0 = tanh(x @ Rw^T + rb), writes history[0] + tsum
    god_gemm<<<dim3(64, 4), 256, SMEM_DYN>>>(
        xhi, xlo, rhi, rlo, D_INPUT,
        nullptr, rb, hist, nullptr, 0,
        zhi[0], zlo[0], tsum, 1);

    // 3) ticks (K=8192, area-gated)
    int p = 0;
    for (int t = 0; t < NTICKS; t++) {
        gate_bias_kernel<<<1, 256>>>(bb);
        god_gemm<<<dim3(64, 4), 256, SMEM_DYN>>>(
            zhi[p], zlo[p], whi, wlo, NTOT,
            gatev, biasv, hist + (size_t)(t + 1) * HIST_STEP, nullptr, 0,
            zhi[1 - p], zlo[1 - p], tsum, 1);
        p ^= 1;
    }

    // 4) logits = Z @ Owg^T + Ob
    god_gemm<<<dim3(8, 4), 256, SMEM_DYN>>>(
        zhi[p], zlo[p], ohi, olo, NTOT,
        nullptr, Ob, nullptr, out, NCLS,
        nullptr, nullptr, nullptr, 0);
}

// round 5
// speedup vs baseline: 3.1500x; 2.0995x over previous
#include <cuda_runtime.h>
#include <cuda_bf16.h>
#include <math.h>
#include <stdint.h>

// ---------------------------------------------------------------------------
// GodAreaModel via mma.sync bf16 (3-term split => fp32 accuracy).
// R4: BK=64, 3-stage cp.async pipeline, 1 sync/iter, split-K logits.
// ---------------------------------------------------------------------------

#define A_NUM   4
#define AREA_N  2048
#define NTOT    8192
#define D_INPUT 1024
#define NCLS    1024
#define BATCH   512
#define NTICKS  4
#define THRESH  0.05f
#define LOGITS_ELEMS (BATCH * NCLS)
#define HIST_STEP    (A_NUM * BATCH * AREA_N)

// Block tile
#define BM 128
#define BN 128
#define BK 64
#define TILE_BYTES (BM * BK * 2)            // 16384 per operand tile
#define STAGE_BYTES (4 * TILE_BYTES)        // Ahi,Alo,Bhi,Blo = 64KB
#define NSTAGE 3
#define SMEM_DYN (NSTAGE * STAGE_BYTES)     // 192KB

#define LOG_SPLIT 4
#define LOG_KTILES (NTOT / BK / LOG_SPLIT)  // 32 tiles per split

// ------------------------- device scratch -------------------------
__device__ __align__(256) __nv_bfloat16 g_Whi[(size_t)NTOT * NTOT];
__device__ __align__(256) __nv_bfloat16 g_Wlo[(size_t)NTOT * NTOT];
__device__ __align__(256) __nv_bfloat16 g_Rhi[(size_t)NTOT * D_INPUT];
__device__ __align__(256) __nv_bfloat16 g_Rlo[(size_t)NTOT * D_INPUT];
__device__ __align__(256) __nv_bfloat16 g_Ohi[(size_t)NCLS * NTOT];
__device__ __align__(256) __nv_bfloat16 g_Olo[(size_t)NCLS * NTOT];
__device__ __align__(256) __nv_bfloat16 g_xhi[(size_t)BATCH * D_INPUT];
__device__ __align__(256) __nv_bfloat16 g_xlo[(size_t)BATCH * D_INPUT];
__device__ __align__(256) __nv_bfloat16 g_Zhi0[(size_t)BATCH * NTOT];
__device__ __align__(256) __nv_bfloat16 g_Zlo0[(size_t)BATCH * NTOT];
__device__ __align__(256) __nv_bfloat16 g_Zhi1[(size_t)BATCH * NTOT];
__device__ __align__(256) __nv_bfloat16 g_Zlo1[(size_t)BATCH * NTOT];
__device__ __align__(256) float g_part[(size_t)LOG_SPLIT * LOGITS_ELEMS];
__device__ __align__(256) float g_tsum[256];
__device__ __align__(256) float g_gatev[A_NUM];
__device__ __align__(256) float g_biasv[NTOT];

// ------------------------- helpers -------------------------
__device__ __forceinline__ uint32_t smem_u32(const void* p) {
    return (uint32_t)__cvta_generic_to_shared(p);
}
__device__ __forceinline__ uint32_t pack2(__nv_bfloat16 a, __nv_bfloat16 b) {
    __nv_bfloat162 v; v.x = a; v.y = b;
    return *reinterpret_cast<uint32_t*>(&v);
}
__device__ __forceinline__ void split_bf16(float w, __nv_bfloat16& h, __nv_bfloat16& l) {
    h = __float2bfloat16(w);
    l = __float2bfloat16(w - __bfloat162float(h));
}
__device__ __forceinline__ void cp16(uint32_t saddr, const void* g) {
    asm volatile("cp.async.cg.shared.global [%0], [%1], 16;" :: "r"(saddr), "l"(g));
}
// swizzled byte offset within a 128x64 bf16 tile (rows of 128B, 8x16B chunks)
__device__ __forceinline__ uint32_t swz(uint32_t row, uint32_t chunk) {
    return row * 128u + ((chunk ^ (row & 7u)) << 4);
}
__device__ __forceinline__ void ldsm4(uint32_t addr, uint32_t* r) {
    asm volatile("ldmatrix.sync.aligned.m8n8.x4.shared.b16 {%0,%1,%2,%3}, [%4];"
                 : "=r"(r[0]), "=r"(r[1]), "=r"(r[2]), "=r"(r[3]) : "r"(addr));
}
__device__ __forceinline__ void mma16816(float* c, const uint32_t* a, const uint32_t* b) {
    asm volatile(
        "mma.sync.aligned.m16n8k16.row.col.f32.bf16.bf16.f32 "
        "{%0,%1,%2,%3}, {%4,%5,%6,%7}, {%8,%9}, {%0,%1,%2,%3};"
        : "+f"(c[0]), "+f"(c[1]), "+f"(c[2]), "+f"(c[3])
        : "r"(a[0]), "r"(a[1]), "r"(a[2]), "r"(a[3]), "r"(b[0]), "r"(b[1]));
}

// ------------------------- prep kernels -------------------------
__global__ void prep_wsplit(const float* __restrict__ W, const float* __restrict__ mask) {
    size_t t = (size_t)blockIdx.x * blockDim.x + threadIdx.x;
    size_t s = t * 2;
    float2 w  = *(const float2*)(W + s);
    float2 mk = *(const float2*)(mask + s);
    float w0 = w.x * fminf(fmaxf(mk.x, 0.f), 1.f);
    float w1 = w.y * fminf(fmaxf(mk.y, 0.f), 1.f);
    int m = (int)(s & 2047);
    size_t r = s >> 11;
    int n = (int)(r & 2047); r >>= 11;
    int i = (int)(r & 3);
    int o = (int)(r >> 2);
    size_t dst = ((size_t)((o << 11) | n)) * NTOT + ((i << 11) | m);
    __nv_bfloat16 h0, l0, h1, l1;
    split_bf16(w0, h0, l0); split_bf16(w1, h1, l1);
    *(uint32_t*)(g_Whi + dst) = pack2(h0, h1);
    *(uint32_t*)(g_Wlo + dst) = pack2(l0, l1);
}
__global__ void prep_rsplit(const float* __restrict__ Rw) {
    size_t s = ((size_t)blockIdx.x * blockDim.x + threadIdx.x) * 2;
    float2 w = *(const float2*)(Rw + s);
    __nv_bfloat16 h0, l0, h1, l1;
    split_bf16(w.x, h0, l0); split_bf16(w.y, h1, l1);
    *(uint32_t*)(g_Rhi + s) = pack2(h0, h1);
    *(uint32_t*)(g_Rlo + s) = pack2(l0, l1);
}
__global__ void prep_osplit(const float* __restrict__ Ow, const int* __restrict__ aidx) {
    size_t s = ((size_t)blockIdx.x * blockDim.x + threadIdx.x) * 2;
    int k = (int)(s & 8191);
    int c = (int)(s >> 13);
    float w0 = Ow[(size_t)c * NTOT + aidx[k]];
    float w1 = Ow[(size_t)c * NTOT + aidx[k + 1]];
    __nv_bfloat16 h0, l0, h1, l1;
    split_bf16(w0, h0, l0); split_bf16(w1, h1, l1);
    *(uint32_t*)(g_Ohi + s) = pack2(h0, h1);
    *(uint32_t*)(g_Olo + s) = pack2(l0, l1);
}
__global__ void prep_xsplit(const float* __restrict__ x) {
    size_t s = ((size_t)blockIdx.x * blockDim.x + threadIdx.x) * 2;
    float2 w = *(const float2*)(x + s);
    __nv_bfloat16 h0, l0, h1, l1;
    split_bf16(w.x, h0, l0); split_bf16(w.y, h1, l1);
    *(uint32_t*)(g_xhi + s) = pack2(h0, h1);
    *(uint32_t*)(g_xlo + s) = pack2(l0, l1);
}
// gates + gated bias (tsum layout: [mtile(4)][ntile(64)])
__global__ void gate_bias_kernel(const float* __restrict__ bb) {
    __shared__ float gsh[A_NUM];
    int t = threadIdx.x;
    if (t < A_NUM) {
        float s = 0.0f;
        for (int mt = 0; mt < 4; mt++)
            for (int nt = t * 16; nt < t * 16 + 16; nt++)
                s += g_tsum[mt * 64 + nt];
        float mean = s * (1.0f / (float)(BATCH * AREA_N));
        float g = (mean > THRESH) ? 1.0f : 0.0f;
        g_gatev[t] = g;
        gsh[t] = g;
    }
    __syncthreads();
    for (int p = t; p < NTOT; p += 256) {
        int o = p >> 11, n = p & 2047;
        float s = 0.0f;
        #pragma unroll
        for (int i = 0; i < A_NUM; i++)
            s += gsh[i] * bb[(o * A_NUM + i) * AREA_N + n];
        g_biasv[p] = s;
    }
}
// logits reduce: out = sum_s part[s] + Ob
__global__ void logits_reduce(const float* __restrict__ Ob, float* __restrict__ out) {
    int i = (blockIdx.x * 256 + threadIdx.x) * 4;
    float4 a = *(const float4*)(g_part + i);
    #pragma unroll
    for (int s = 1; s < LOG_SPLIT; s++) {
        float4 b = *(const float4*)(g_part + (size_t)s * LOGITS_ELEMS + i);
        a.x += b.x; a.y += b.y; a.z += b.z; a.w += b.w;
    }
    int n = i & (NCLS - 1);
    float4 ob = *(const float4*)(Ob + n);
    a.x += ob.x; a.y += ob.y; a.z += ob.z; a.w += ob.w;
    *(float4*)(out + i) = a;
}

// ------------------------- stage loader -------------------------
__device__ __forceinline__ void load_tile(uint32_t sb, const __nv_bfloat16* g, int ld, int tid) {
    #pragma unroll
    for (int r = 0; r < 4; r++) {
        int id = tid + r * 256;
        uint32_t row = (uint32_t)id >> 3, c = (uint32_t)id & 7;
        cp16(sb + swz(row, c), g + (size_t)row * ld + c * 8);
    }
}
__device__ __forceinline__ void load_stage(
    uint32_t sb,
    const __nv_bfloat16* Ahi, const __nv_bfloat16* Alo,
    const __nv_bfloat16* Bhi, const __nv_bfloat16* Blo,
    int m0, int n0, int k0, int ld, int tid)
{
    load_tile(sb,                  Ahi + (size_t)m0 * ld + k0, ld, tid);
    load_tile(sb + TILE_BYTES,     Alo + (size_t)m0 * ld + k0, ld, tid);
    load_tile(sb + 2 * TILE_BYTES, Bhi + (size_t)n0 * ld + k0, ld, tid);
    load_tile(sb + 3 * TILE_BYTES, Blo + (size_t)n0 * ld + k0, ld, tid);
    asm volatile("cp.async.commit_group;" ::: "memory");
}

// ------------------------- main GEMM -------------------------
__global__ __launch_bounds__(256, 1)
void god_gemm(const __nv_bfloat16* __restrict__ Ahi, const __nv_bfloat16* __restrict__ Alo,
              const __nv_bfloat16* __restrict__ Bhi, const __nv_bfloat16* __restrict__ Blo,
              int ldk, int ktiles_in, int k0tile,
              const float* __restrict__ gate,
              const float* __restrict__ bias,
              float* __restrict__ hist,
              float* __restrict__ logits, int logitsN,
              __nv_bfloat16* __restrict__ Zho, __nv_bfloat16* __restrict__ Zlo_out,
              float* __restrict__ tsum,
              int do_tanh)
{
    extern __shared__ char dsm[];
    __shared__ float s_wsum[8];

    const int tid  = threadIdx.x;
    const int wid  = tid >> 5, lane = tid & 31;
    const int wm   = wid >> 2;
    const int wn   = wid & 3;
    const int m0   = blockIdx.y * BM;
    const int n0   = blockIdx.x * BN;
    const uint32_t sbase = smem_u32(dsm);

    // active-area map (uniform across CTA; no smem, no serial loop)
    int aa[A_NUM];
    int nact;
    if (gate) {
        int c = 0;
        #pragma unroll
        for (int a = 0; a < A_NUM; a++)
            if (__ldg(gate + a) != 0.0f) aa[c++] = a;
        nact = c * 32;                 // 32 BK-tiles per area
    } else {
        nact = ktiles_in;
        aa[0] = 0;
    }
    #define KT(i) (gate ? (aa[(i) >> 5] * 32 + ((i) & 31)) : (k0tile + (i)))

    float acc[4][4][4];
    #pragma unroll
    for (int a = 0; a < 4; a++)
        #pragma unroll
        for (int b = 0; b < 4; b++)
            #pragma unroll
            for (int c = 0; c < 4; c++) acc[a][b][c] = 0.0f;

    const uint32_t a_row = (lane & 7) + ((lane >> 3) & 1) * 8;
    const uint32_t a_ch  = (lane >> 4);
    const uint32_t b_row = (lane & 7) + (lane >> 4) * 8;
    const uint32_t b_ch  = (lane >> 3) & 1;

    if (nact > 0)
        load_stage(sbase, Ahi, Alo, Bhi, Blo, m0, n0, KT(0) * BK, ldk, tid);
    if (nact > 1)
        load_stage(sbase + STAGE_BYTES, Ahi, Alo, Bhi, Blo, m0, n0, KT(1) * BK, ldk, tid);

    int sl = 0;   // stage of iter i
    #pragma unroll 1
    for (int i = 0; i < nact; i++) {
        if (i + 1 < nact) { asm volatile("cp.async.wait_group 1;" ::: "memory"); }
        else              { asm volatile("cp.async.wait_group 0;" ::: "memory"); }
        __syncthreads();

        if (i + 2 < nact) {
            int s2 = sl + 2; if (s2 >= NSTAGE) s2 -= NSTAGE;
            load_stage(sbase + (uint32_t)s2 * STAGE_BYTES,
                       Ahi, Alo, Bhi, Blo, m0, n0, KT(i + 2) * BK, ldk, tid);
        }

        const uint32_t sb  = sbase + (uint32_t)sl * STAGE_BYTES;
        const uint32_t sA  = sb;
        const uint32_t sAl = sb + TILE_BYTES;
        const uint32_t sB  = sb + 2 * TILE_BYTES;
        const uint32_t sBl = sb + 3 * TILE_BYTES;

        #pragma unroll
        for (int ks = 0; ks < 4; ks++) {
            uint32_t ah[4][4], al[4][4];
            #pragma unroll
            for (int mt = 0; mt < 4; mt++) {
                uint32_t row = wm * 64 + mt * 16 + a_row;
                uint32_t off = swz(row, ks * 2 + a_ch);
                ldsm4(sA + off, ah[mt]);
                ldsm4(sAl + off, al[mt]);
            }
            uint32_t bh[2][4], bl[2][4];
            #pragma unroll
            for (int ng = 0; ng < 2; ng++) {
                uint32_t row = wn * 32 + ng * 16 + b_row;
                uint32_t off = swz(row, ks * 2 + b_ch);
                ldsm4(sB + off, bh[ng]);
                ldsm4(sBl + off, bl[ng]);
            }
            #pragma unroll
            for (int mt = 0; mt < 4; mt++)
                #pragma unroll
                for (int nt = 0; nt < 4; nt++) {
                    const uint32_t* bph = bh[nt >> 1] + (nt & 1) * 2;
                    const uint32_t* bpl = bl[nt >> 1] + (nt & 1) * 2;
                    mma16816(acc[mt][nt], ah[mt], bph);
                    mma16816(acc[mt][nt], al[mt], bph);
                    mma16816(acc[mt][nt], ah[mt], bpl);
                }
        }
        sl++; if (sl == NSTAGE) sl = 0;
    }

    // ---- epilogue ----
    float asum = 0.0f;
    const int lrow = lane >> 2;
    const int lcol = (lane & 3) * 2;
    #pragma unroll
    for (int mt = 0; mt < 4; mt++) {
        #pragma unroll
        for (int half = 0; half < 2; half++) {
            const int m = m0 + wm * 64 + mt * 16 + lrow + half * 8;
            #pragma unroll
            for (int nt = 0; nt < 4; nt++) {
                const int n = n0 + wn * 32 + nt * 8 + lcol;
                float v0 = acc[mt][nt][half * 2 + 0] + (bias ? __ldg(bias + n) : 0.0f);
                float v1 = acc[mt][nt][half * 2 + 1] + (bias ? __ldg(bias + n + 1) : 0.0f);
                if (do_tanh) { v0 = tanhf(v0); v1 = tanhf(v1); }
                asum += fabsf(v0) + fabsf(v1);
                if (hist) {
                    int a = n >> 11, nn = n & 2047;
                    *(float2*)(hist + ((size_t)a * BATCH + m) * AREA_N + nn) =
                        make_float2(v0, v1);
                }
                if (logits)
                    *(float2*)(logits + (size_t)m * logitsN + n) = make_float2(v0, v1);
                if (Zho) {
                    __nv_bfloat16 h0, l0, h1, l1;
                    split_bf16(v0, h0, l0); split_bf16(v1, h1, l1);
                    *(uint32_t*)(Zho     + (size_t)m * NTOT + n) = pack2(h0, h1);
                    *(uint32_t*)(Zlo_out + (size_t)m * NTOT + n) = pack2(l0, l1);
                }
            }
        }
    }

    if (tsum) {
        #pragma unroll
        for (int o = 16; o; o >>= 1) asum += __shfl_xor_sync(0xffffffffu, asum, o);
        if (lane == 0) s_wsum[wid] = asum;
        __syncthreads();
        if (tid == 0) {
            float s = ((s_wsum[0] + s_wsum[1]) + (s_wsum[2] + s_wsum[3]))
                    + ((s_wsum[4] + s_wsum[5]) + (s_wsum[6] + s_wsum[7]));
            tsum[blockIdx.y * 64 + blockIdx.x] = s;
        }
    }
}

// ------------------------- launch -------------------------
extern "C" void kernel_launch(void* const* d_in, const int* in_sizes, int n_in,
                              void* d_out, int out_size) {
    const float* x    = (const float*)d_in[0];
    const float* Rw   = (const float*)d_in[1];
    const float* rb   = (const float*)d_in[2];
    const float* Wb   = (const float*)d_in[3];
    const float* bb   = (const float*)d_in[4];
    const float* mask = (const float*)d_in[5];
    const float* Ow   = (const float*)d_in[6];
    const float* Ob   = (const float*)d_in[7];
    const int*   aidx = (const int*)d_in[8];

    float* out  = (float*)d_out;
    float* hist = out + LOGITS_ELEMS;

    __nv_bfloat16 *whi, *wlo, *rhi, *rlo, *ohi, *olo, *xhi, *xlo;
    __nv_bfloat16 *zhi[2], *zlo[2];
    float *tsum, *gatev, *biasv, *part;
    cudaGetSymbolAddress((void**)&whi, g_Whi);
    cudaGetSymbolAddress((void**)&wlo, g_Wlo);
    cudaGetSymbolAddress((void**)&rhi, g_Rhi);
    cudaGetSymbolAddress((void**)&rlo, g_Rlo);
    cudaGetSymbolAddress((void**)&ohi, g_Ohi);
    cudaGetSymbolAddress((void**)&olo, g_Olo);
    cudaGetSymbolAddress((void**)&xhi, g_xhi);
    cudaGetSymbolAddress((void**)&xlo, g_xlo);
    cudaGetSymbolAddress((void**)&zhi[0], g_Zhi0);
    cudaGetSymbolAddress((void**)&zlo[0], g_Zlo0);
    cudaGetSymbolAddress((void**)&zhi[1], g_Zhi1);
    cudaGetSymbolAddress((void**)&zlo[1], g_Zlo1);
    cudaGetSymbolAddress((void**)&tsum,  g_tsum);
    cudaGetSymbolAddress((void**)&gatev, g_gatev);
    cudaGetSymbolAddress((void**)&biasv, g_biasv);
    cudaGetSymbolAddress((void**)&part,  g_part);

    cudaFuncSetAttribute(god_gemm, cudaFuncAttributeMaxDynamicSharedMemorySize, SMEM_DYN);

    // 1) split/prep
    prep_wsplit<<<131072, 256>>>(Wb, mask);
    prep_rsplit<<<16384, 256>>>(Rw);
    prep_osplit<<<16384, 256>>>(Ow, aidx);
    prep_xsplit<<<1024, 256>>>(x);

    // 2) encode (K=1024)
    god_gemm<<<dim3(64, 4), 256, SMEM_DYN>>>(
        xhi, xlo, rhi, rlo, D_INPUT, D_INPUT / BK, 0,
        nullptr, rb, hist, nullptr, 0,
        zhi[0], zlo[0], tsum, 1);

    // 3) ticks (K=8192, area-gated)
    int p = 0;
    for (int t = 0; t < NTICKS; t++) {
        gate_bias_kernel<<<1, 256>>>(bb);
        god_gemm<<<dim3(64, 4), 256, SMEM_DYN>>>(
            zhi[p], zlo[p], whi, wlo, NTOT, 0, 0,
            gatev, biasv, hist + (size_t)(t + 1) * HIST_STEP, nullptr, 0,
            zhi[1 - p], zlo[1 - p], tsum, 1);
        p ^= 1;
    }

    // 4) logits: split-K partials, then deterministic reduce (+Ob)
    for (int s = 0; s < LOG_SPLIT; s++) {
        god_gemm<<<dim3(8, 4), 256, SMEM_DYN>>>(
            zhi[p], zlo[p], ohi, olo, NTOT, LOG_KTILES, s * LOG_KTILES,
            nullptr, nullptr, nullptr, part + (size_t)s * LOGITS_ELEMS, NCLS,
            nullptr, nullptr, nullptr, 0);
    }
    logits_reduce<<<LOGITS_ELEMS / 1024, 256>>>(Ob, out);
}

// round 6
// speedup vs baseline: 3.7766x; 1.1989x over previous
#include <cuda_runtime.h>
#include <cuda_bf16.h>
#include <math.h>
#include <stdint.h>

// ---------------------------------------------------------------------------
// GodAreaModel via mma.sync bf16 (3-term split => fp32 accuracy).
// R5: BM=256/BN=128, warp tile 64x64 (3x less smem traffic), 1-wave grids,
//     concurrent split-K logits.
// ---------------------------------------------------------------------------

#define A_NUM   4
#define AREA_N  2048
#define NTOT    8192
#define D_INPUT 1024
#define NCLS    1024
#define BATCH   512
#define NTICKS  4
#define THRESH  0.05f
#define LOGITS_ELEMS (BATCH * NCLS)
#define HIST_STEP    (A_NUM * BATCH * AREA_N)

// Block tile
#define BM 256
#define BN 128
#define BK 64
#define A_TILE_BYTES (BM * BK * 2)          // 32768
#define B_TILE_BYTES (BN * BK * 2)          // 16384
#define STAGE_BYTES (2 * A_TILE_BYTES + 2 * B_TILE_BYTES)  // 98304
#define NSTAGE 2
#define SMEM_DYN (NSTAGE * STAGE_BYTES)     // 196608

#define LOG_SPLIT 8
#define LOG_KTILES (NTOT / BK / LOG_SPLIT)  // 16 tiles per split

// ------------------------- device scratch -------------------------
__device__ __align__(256) __nv_bfloat16 g_Whi[(size_t)NTOT * NTOT];
__device__ __align__(256) __nv_bfloat16 g_Wlo[(size_t)NTOT * NTOT];
__device__ __align__(256) __nv_bfloat16 g_Rhi[(size_t)NTOT * D_INPUT];
__device__ __align__(256) __nv_bfloat16 g_Rlo[(size_t)NTOT * D_INPUT];
__device__ __align__(256) __nv_bfloat16 g_Ohi[(size_t)NCLS * NTOT];
__device__ __align__(256) __nv_bfloat16 g_Olo[(size_t)NCLS * NTOT];
__device__ __align__(256) __nv_bfloat16 g_xhi[(size_t)BATCH * D_INPUT];
__device__ __align__(256) __nv_bfloat16 g_xlo[(size_t)BATCH * D_INPUT];
__device__ __align__(256) __nv_bfloat16 g_Zhi0[(size_t)BATCH * NTOT];
__device__ __align__(256) __nv_bfloat16 g_Zlo0[(size_t)BATCH * NTOT];
__device__ __align__(256) __nv_bfloat16 g_Zhi1[(size_t)BATCH * NTOT];
__device__ __align__(256) __nv_bfloat16 g_Zlo1[(size_t)BATCH * NTOT];
__device__ __align__(256) float g_part[(size_t)LOG_SPLIT * LOGITS_ELEMS];
__device__ __align__(256) float g_tsum[256];
__device__ __align__(256) float g_gatev[A_NUM];
__device__ __align__(256) float g_biasv[NTOT];

// ------------------------- helpers -------------------------
__device__ __forceinline__ uint32_t smem_u32(const void* p) {
    return (uint32_t)__cvta_generic_to_shared(p);
}
__device__ __forceinline__ uint32_t pack2(__nv_bfloat16 a, __nv_bfloat16 b) {
    __nv_bfloat162 v; v.x = a; v.y = b;
    return *reinterpret_cast<uint32_t*>(&v);
}
__device__ __forceinline__ void split_bf16(float w, __nv_bfloat16& h, __nv_bfloat16& l) {
    h = __float2bfloat16(w);
    l = __float2bfloat16(w - __bfloat162float(h));
}
__device__ __forceinline__ void cp16(uint32_t saddr, const void* g) {
    asm volatile("cp.async.cg.shared.global [%0], [%1], 16;" :: "r"(saddr), "l"(g));
}
// swizzled byte offset within a [rows x 64] bf16 tile (rows of 128B, 8x16B chunks)
__device__ __forceinline__ uint32_t swz(uint32_t row, uint32_t chunk) {
    return row * 128u + ((chunk ^ (row & 7u)) << 4);
}
__device__ __forceinline__ void ldsm4(uint32_t addr, uint32_t* r) {
    asm volatile("ldmatrix.sync.aligned.m8n8.x4.shared.b16 {%0,%1,%2,%3}, [%4];"
                 : "=r"(r[0]), "=r"(r[1]), "=r"(r[2]), "=r"(r[3]) : "r"(addr));
}
__device__ __forceinline__ void mma16816(float* c, const uint32_t* a, const uint32_t* b) {
    asm volatile(
        "mma.sync.aligned.m16n8k16.row.col.f32.bf16.bf16.f32 "
        "{%0,%1,%2,%3}, {%4,%5,%6,%7}, {%8,%9}, {%0,%1,%2,%3};"
        : "+f"(c[0]), "+f"(c[1]), "+f"(c[2]), "+f"(c[3])
        : "r"(a[0]), "r"(a[1]), "r"(a[2]), "r"(a[3]), "r"(b[0]), "r"(b[1]));
}

// ------------------------- prep kernels -------------------------
__global__ void prep_wsplit(const float* __restrict__ W, const float* __restrict__ mask) {
    size_t t = (size_t)blockIdx.x * blockDim.x + threadIdx.x;
    size_t s = t * 2;
    float2 w  = *(const float2*)(W + s);
    float2 mk = *(const float2*)(mask + s);
    float w0 = w.x * fminf(fmaxf(mk.x, 0.f), 1.f);
    float w1 = w.y * fminf(fmaxf(mk.y, 0.f), 1.f);
    int m = (int)(s & 2047);
    size_t r = s >> 11;
    int n = (int)(r & 2047); r >>= 11;
    int i = (int)(r & 3);
    int o = (int)(r >> 2);
    size_t dst = ((size_t)((o << 11) | n)) * NTOT + ((i << 11) | m);
    __nv_bfloat16 h0, l0, h1, l1;
    split_bf16(w0, h0, l0); split_bf16(w1, h1, l1);
    *(uint32_t*)(g_Whi + dst) = pack2(h0, h1);
    *(uint32_t*)(g_Wlo + dst) = pack2(l0, l1);
}
__global__ void prep_rsplit(const float* __restrict__ Rw) {
    size_t s = ((size_t)blockIdx.x * blockDim.x + threadIdx.x) * 2;
    float2 w = *(const float2*)(Rw + s);
    __nv_bfloat16 h0, l0, h1, l1;
    split_bf16(w.x, h0, l0); split_bf16(w.y, h1, l1);
    *(uint32_t*)(g_Rhi + s) = pack2(h0, h1);
    *(uint32_t*)(g_Rlo + s) = pack2(l0, l1);
}
__global__ void prep_osplit(const float* __restrict__ Ow, const int* __restrict__ aidx) {
    size_t s = ((size_t)blockIdx.x * blockDim.x + threadIdx.x) * 2;
    int k = (int)(s & 8191);
    int c = (int)(s >> 13);
    float w0 = Ow[(size_t)c * NTOT + aidx[k]];
    float w1 = Ow[(size_t)c * NTOT + aidx[k + 1]];
    __nv_bfloat16 h0, l0, h1, l1;
    split_bf16(w0, h0, l0); split_bf16(w1, h1, l1);
    *(uint32_t*)(g_Ohi + s) = pack2(h0, h1);
    *(uint32_t*)(g_Olo + s) = pack2(l0, l1);
}
__global__ void prep_xsplit(const float* __restrict__ x) {
    size_t s = ((size_t)blockIdx.x * blockDim.x + threadIdx.x) * 2;
    float2 w = *(const float2*)(x + s);
    __nv_bfloat16 h0, l0, h1, l1;
    split_bf16(w.x, h0, l0); split_bf16(w.y, h1, l1);
    *(uint32_t*)(g_xhi + s) = pack2(h0, h1);
    *(uint32_t*)(g_xlo + s) = pack2(l0, l1);
}
// gates + gated bias. tsum layout: [mtile(2)][ntile(64)], area a = ntiles [16a,16a+16)
__global__ void gate_bias_kernel(const float* __restrict__ bb) {
    __shared__ float gsh[A_NUM];
    int t = threadIdx.x;
    if (t < A_NUM) {
        float s = 0.0f;
        for (int mt = 0; mt < 2; mt++)
            for (int nt = t * 16; nt < t * 16 + 16; nt++)
                s += g_tsum[mt * 64 + nt];
        float mean = s * (1.0f / (float)(BATCH * AREA_N));
        float g = (mean > THRESH) ? 1.0f : 0.0f;
        g_gatev[t] = g;
        gsh[t] = g;
    }
    __syncthreads();
    for (int p = t; p < NTOT; p += 256) {
        int o = p >> 11, n = p & 2047;
        float s = 0.0f;
        #pragma unroll
        for (int i = 0; i < A_NUM; i++)
            s += gsh[i] * bb[(o * A_NUM + i) * AREA_N + n];
        g_biasv[p] = s;
    }
}
// logits reduce: out = sum_s part[s] + Ob
__global__ void logits_reduce(const float* __restrict__ Ob, float* __restrict__ out) {
    int i = (blockIdx.x * 256 + threadIdx.x) * 4;
    float4 a = *(const float4*)(g_part + i);
    #pragma unroll
    for (int s = 1; s < LOG_SPLIT; s++) {
        float4 b = *(const float4*)(g_part + (size_t)s * LOGITS_ELEMS + i);
        a.x += b.x; a.y += b.y; a.z += b.z; a.w += b.w;
    }
    int n = i & (NCLS - 1);
    float4 ob = *(const float4*)(Ob + n);
    a.x += ob.x; a.y += ob.y; a.z += ob.z; a.w += ob.w;
    *(float4*)(out + i) = a;
}

// ------------------------- stage loader -------------------------
__device__ __forceinline__ void load_tileA(uint32_t sb, const __nv_bfloat16* g, int ld, int tid) {
    #pragma unroll
    for (int r = 0; r < 8; r++) {
        int id = tid + r * 256;
        uint32_t row = (uint32_t)id >> 3, c = (uint32_t)id & 7;
        cp16(sb + swz(row, c), g + (size_t)row * ld + c * 8);
    }
}
__device__ __forceinline__ void load_tileB(uint32_t sb, const __nv_bfloat16* g, int ld, int tid) {
    #pragma unroll
    for (int r = 0; r < 4; r++) {
        int id = tid + r * 256;
        uint32_t row = (uint32_t)id >> 3, c = (uint32_t)id & 7;
        cp16(sb + swz(row, c), g + (size_t)row * ld + c * 8);
    }
}
__device__ __forceinline__ void load_stage(
    uint32_t sb,
    const __nv_bfloat16* Ahi, const __nv_bfloat16* Alo,
    const __nv_bfloat16* Bhi, const __nv_bfloat16* Blo,
    int m0, int n0, int k0, int ld, int tid)
{
    load_tileA(sb,                    Ahi + (size_t)m0 * ld + k0, ld, tid);
    load_tileA(sb + A_TILE_BYTES,     Alo + (size_t)m0 * ld + k0, ld, tid);
    load_tileB(sb + 2 * A_TILE_BYTES, Bhi + (size_t)n0 * ld + k0, ld, tid);
    load_tileB(sb + 2 * A_TILE_BYTES + B_TILE_BYTES, Blo + (size_t)n0 * ld + k0, ld, tid);
    asm volatile("cp.async.commit_group;" ::: "memory");
}

// ------------------------- main GEMM -------------------------
// grid (N/BN, M/BM, zsplit). Warp layout: 4(m) x 2(n), warp tile 64x64.
__global__ __launch_bounds__(256, 1)
void god_gemm(const __nv_bfloat16* __restrict__ Ahi, const __nv_bfloat16* __restrict__ Alo,
              const __nv_bfloat16* __restrict__ Bhi, const __nv_bfloat16* __restrict__ Blo,
              int ldk, int ktiles_in,
              const float* __restrict__ gate,
              const float* __restrict__ bias,
              float* __restrict__ hist,
              float* __restrict__ logits, int logitsN, size_t zstride,
              __nv_bfloat16* __restrict__ Zho, __nv_bfloat16* __restrict__ Zlo_out,
              float* __restrict__ tsum,
              int do_tanh)
{
    extern __shared__ char dsm[];
    __shared__ float s_wsum[8];

    const int tid  = threadIdx.x;
    const int wid  = tid >> 5, lane = tid & 31;
    const int wm   = wid >> 1;          // 0..3 -> 64-row slab
    const int wn   = wid & 1;           // 0..1 -> 64-col slab
    const int m0   = blockIdx.y * BM;
    const int n0   = blockIdx.x * BN;
    const int k0tile = blockIdx.z * ktiles_in;
    const uint32_t sbase = smem_u32(dsm);
    if (logits) logits += (size_t)blockIdx.z * zstride;

    // active-area map (uniform; area = 32 BK-tiles)
    int aa[A_NUM];
    int nact;
    if (gate) {
        int c = 0;
        #pragma unroll
        for (int a = 0; a < A_NUM; a++)
            if (__ldg(gate + a) != 0.0f) aa[c++] = a;
        nact = c * 32;
    } else {
        nact = ktiles_in;
        aa[0] = 0;
    }
    #define KT(i) (gate ? (aa[(i) >> 5] * 32 + ((i) & 31)) : (k0tile + (i)))

    float acc[4][8][4];
    #pragma unroll
    for (int a = 0; a < 4; a++)
        #pragma unroll
        for (int b = 0; b < 8; b++)
            #pragma unroll
            for (int c = 0; c < 4; c++) acc[a][b][c] = 0.0f;

    const uint32_t a_row = (lane & 7) + ((lane >> 3) & 1) * 8;
    const uint32_t a_ch  = (lane >> 4);
    const uint32_t b_row = (lane & 7) + (lane >> 4) * 8;
    const uint32_t b_ch  = (lane >> 3) & 1;

    if (nact > 0)
        load_stage(sbase, Ahi, Alo, Bhi, Blo, m0, n0, KT(0) * BK, ldk, tid);

    #pragma unroll 1
    for (int i = 0; i < nact; i++) {
        asm volatile("cp.async.wait_group 0;" ::: "memory");
        __syncthreads();

        if (i + 1 < nact)
            load_stage(sbase + (uint32_t)((i + 1) & 1) * STAGE_BYTES,
                       Ahi, Alo, Bhi, Blo, m0, n0, KT(i + 1) * BK, ldk, tid);

        const uint32_t sb  = sbase + (uint32_t)(i & 1) * STAGE_BYTES;
        const uint32_t sA  = sb;
        const uint32_t sAl = sb + A_TILE_BYTES;
        const uint32_t sB  = sb + 2 * A_TILE_BYTES;
        const uint32_t sBl = sb + 2 * A_TILE_BYTES + B_TILE_BYTES;

        #pragma unroll
        for (int ks = 0; ks < 4; ks++) {
            uint32_t bh[4][4], bl[4][4];
            #pragma unroll
            for (int ng = 0; ng < 4; ng++) {
                uint32_t row = wn * 64 + ng * 16 + b_row;
                uint32_t off = swz(row, ks * 2 + b_ch);
                ldsm4(sB + off, bh[ng]);
                ldsm4(sBl + off, bl[ng]);
            }
            #pragma unroll
            for (int mt = 0; mt < 4; mt++) {
                uint32_t ah[4], al[4];
                uint32_t row = wm * 64 + mt * 16 + a_row;
                uint32_t off = swz(row, ks * 2 + a_ch);
                ldsm4(sA + off, ah);
                ldsm4(sAl + off, al);
                #pragma unroll
                for (int nt = 0; nt < 8; nt++) {
                    const uint32_t* bph = bh[nt >> 1] + (nt & 1) * 2;
                    const uint32_t* bpl = bl[nt >> 1] + (nt & 1) * 2;
                    mma16816(acc[mt][nt], ah, bph);
                    mma16816(acc[mt][nt], al, bph);
                    mma16816(acc[mt][nt], ah, bpl);
                }
            }
        }
    }

    // ---- epilogue ----
    float asum = 0.0f;
    const int lrow = lane >> 2;
    const int lcol = (lane & 3) * 2;
    #pragma unroll
    for (int mt = 0; mt < 4; mt++) {
        #pragma unroll
        for (int half = 0; half < 2; half++) {
            const int m = m0 + wm * 64 + mt * 16 + lrow + half * 8;
            #pragma unroll
            for (int nt = 0; nt < 8; nt++) {
                const int n = n0 + wn * 64 + nt * 8 + lcol;
                float v0 = acc[mt][nt][half * 2 + 0] + (bias ? __ldg(bias + n) : 0.0f);
                float v1 = acc[mt][nt][half * 2 + 1] + (bias ? __ldg(bias + n + 1) : 0.0f);
                if (do_tanh) { v0 = tanhf(v0); v1 = tanhf(v1); }
                asum += fabsf(v0) + fabsf(v1);
                if (hist) {
                    int a = n >> 11, nn = n & 2047;
                    *(float2*)(hist + ((size_t)a * BATCH + m) * AREA_N + nn) =
                        make_float2(v0, v1);
                }
                if (logits)
                    *(float2*)(logits + (size_t)m * logitsN + n) = make_float2(v0, v1);
                if (Zho) {
                    __nv_bfloat16 h0, l0, h1, l1;
                    split_bf16(v0, h0, l0); split_bf16(v1, h1, l1);
                    *(uint32_t*)(Zho     + (size_t)m * NTOT + n) = pack2(h0, h1);
                    *(uint32_t*)(Zlo_out + (size_t)m * NTOT + n) = pack2(l0, l1);
                }
            }
        }
    }

    if (tsum) {
        #pragma unroll
        for (int o = 16; o; o >>= 1) asum += __shfl_xor_sync(0xffffffffu, asum, o);
        if (lane == 0) s_wsum[wid] = asum;
        __syncthreads();
        if (tid == 0) {
            float s = ((s_wsum[0] + s_wsum[1]) + (s_wsum[2] + s_wsum[3]))
                    + ((s_wsum[4] + s_wsum[5]) + (s_wsum[6] + s_wsum[7]));
            tsum[blockIdx.y * 64 + blockIdx.x] = s;
        }
    }
}

// ------------------------- launch -------------------------
extern "C" void kernel_launch(void* const* d_in, const int* in_sizes, int n_in,
                              void* d_out, int out_size) {
    const float* x    = (const float*)d_in[0];
    const float* Rw   = (const float*)d_in[1];
    const float* rb   = (const float*)d_in[2];
    const float* Wb   = (const float*)d_in[3];
    const float* bb   = (const float*)d_in[4];
    const float* mask = (const float*)d_in[5];
    const float* Ow   = (const float*)d_in[6];
    const float* Ob   = (const float*)d_in[7];
    const int*   aidx = (const int*)d_in[8];

    float* out  = (float*)d_out;
    float* hist = out + LOGITS_ELEMS;

    __nv_bfloat16 *whi, *wlo, *rhi, *rlo, *ohi, *olo, *xhi, *xlo;
    __nv_bfloat16 *zhi[2], *zlo[2];
    float *tsum, *gatev, *biasv, *part;
    cudaGetSymbolAddress((void**)&whi, g_Whi);
    cudaGetSymbolAddress((void**)&wlo, g_Wlo);
    cudaGetSymbolAddress((void**)&rhi, g_Rhi);
    cudaGetSymbolAddress((void**)&rlo, g_Rlo);
    cudaGetSymbolAddress((void**)&ohi, g_Ohi);
    cudaGetSymbolAddress((void**)&olo, g_Olo);
    cudaGetSymbolAddress((void**)&xhi, g_xhi);
    cudaGetSymbolAddress((void**)&xlo, g_xlo);
    cudaGetSymbolAddress((void**)&zhi[0], g_Zhi0);
    cudaGetSymbolAddress((void**)&zlo[0], g_Zlo0);
    cudaGetSymbolAddress((void**)&zhi[1], g_Zhi1);
    cudaGetSymbolAddress((void**)&zlo[1], g_Zlo1);
    cudaGetSymbolAddress((void**)&tsum,  g_tsum);
    cudaGetSymbolAddress((void**)&gatev, g_gatev);
    cudaGetSymbolAddress((void**)&biasv, g_biasv);
    cudaGetSymbolAddress((void**)&part,  g_part);

    cudaFuncSetAttribute(god_gemm, cudaFuncAttributeMaxDynamicSharedMemorySize, SMEM_DYN);

    // 1) split/prep
    prep_xsplit<<<1024, 256>>>(x);
    prep_rsplit<<<16384, 256>>>(Rw);
    prep_wsplit<<<131072, 256>>>(Wb, mask);
    prep_osplit<<<16384, 256>>>(Ow, aidx);

    // 2) encode (K=1024): grid (64,2) = 128 CTAs, one wave
    god_gemm<<<dim3(64, 2), 256, SMEM_DYN>>>(
        xhi, xlo, rhi, rlo, D_INPUT, D_INPUT / BK,
        nullptr, rb, hist, nullptr, 0, 0,
        zhi[0], zlo[0], tsum, 1);

    // 3) ticks (K=8192, area-gated)
    int p = 0;
    for (int t = 0; t < NTICKS; t++) {
        gate_bias_kernel<<<1, 256>>>(bb);
        god_gemm<<<dim3(64, 2), 256, SMEM_DYN>>>(
            zhi[p], zlo[p], whi, wlo, NTOT, 0,
            gatev, biasv, hist + (size_t)(t + 1) * HIST_STEP, nullptr, 0, 0,
            zhi[1 - p], zlo[1 - p], tsum, 1);
        p ^= 1;
    }

    // 4) logits: one 3D launch, 8-way split-K = 128 concurrent CTAs, then reduce
    god_gemm<<<dim3(8, 2, LOG_SPLIT), 256, SMEM_DYN>>>(
        zhi[p], zlo[p], ohi, olo, NTOT, LOG_KTILES,
        nullptr, nullptr, nullptr, part, NCLS, (size_t)LOGITS_ELEMS,
        nullptr, nullptr, nullptr, 0);
    logits_reduce<<<LOGITS_ELEMS / 1024, 256>>>(Ob, out);
}

// round 7
// speedup vs baseline: 5.1672x; 1.3682x over previous
#include <cuda_runtime.h>
#include <cuda_fp16.h>
#include <math.h>
#include <stdint.h>

// ---------------------------------------------------------------------------
// GodAreaModel via mma.sync fp16, 2-term split: C = Z*Whi + Z*Wlo.
// Z single fp16 (u=2^-11); W hi/lo fp16 (residual ~6e-6). 3-stage cp.async.
// ---------------------------------------------------------------------------

#define A_NUM   4
#define AREA_N  2048
#define NTOT    8192
#define D_INPUT 1024
#define NCLS    1024
#define BATCH   512
#define NTICKS  4
#define THRESH  0.05f
#define LOGITS_ELEMS (BATCH * NCLS)
#define HIST_STEP    (A_NUM * BATCH * AREA_N)

// Block tile
#define BM 256
#define BN 128
#define BK 64
#define A_TILE_BYTES (BM * BK * 2)          // 32768 (single fp16 A)
#define B_TILE_BYTES (BN * BK * 2)          // 16384 (each of hi/lo)
#define STAGE_BYTES (A_TILE_BYTES + 2 * B_TILE_BYTES)  // 65536
#define NSTAGE 3
#define SMEM_DYN (NSTAGE * STAGE_BYTES)     // 196608

#define LOG_SPLIT 8
#define LOG_KTILES (NTOT / BK / LOG_SPLIT)  // 16

// ------------------------- device scratch -------------------------
__device__ __align__(256) __half g_Whi[(size_t)NTOT * NTOT];
__device__ __align__(256) __half g_Wlo[(size_t)NTOT * NTOT];
__device__ __align__(256) __half g_Rhi[(size_t)NTOT * D_INPUT];
__device__ __align__(256) __half g_Rlo[(size_t)NTOT * D_INPUT];
__device__ __align__(256) __half g_Ohi[(size_t)NCLS * NTOT];
__device__ __align__(256) __half g_Olo[(size_t)NCLS * NTOT];
__device__ __align__(256) __half g_xf [(size_t)BATCH * D_INPUT];
__device__ __align__(256) __half g_Zf0[(size_t)BATCH * NTOT];
__device__ __align__(256) __half g_Zf1[(size_t)BATCH * NTOT];
__device__ __align__(256) float g_part[(size_t)LOG_SPLIT * LOGITS_ELEMS];
__device__ __align__(256) float g_tsum[256];
__device__ __align__(256) float g_gatev[A_NUM];
__device__ __align__(256) float g_biasv[NTOT];

// ------------------------- helpers -------------------------
__device__ __forceinline__ uint32_t smem_u32(const void* p) {
    return (uint32_t)__cvta_generic_to_shared(p);
}
__device__ __forceinline__ uint32_t pack2h(__half a, __half b) {
    __half2 v; v.x = a; v.y = b;
    return *reinterpret_cast<uint32_t*>(&v);
}
__device__ __forceinline__ void split_h(float w, __half& h, __half& l) {
    h = __float2half_rn(w);
    l = __float2half_rn(w - __half2float(h));
}
__device__ __forceinline__ void cp16(uint32_t saddr, const void* g) {
    asm volatile("cp.async.cg.shared.global [%0], [%1], 16;" :: "r"(saddr), "l"(g));
}
// swizzled byte offset within a [rows x 64] fp16 tile (rows of 128B, 8x16B chunks)
__device__ __forceinline__ uint32_t swz(uint32_t row, uint32_t chunk) {
    return row * 128u + ((chunk ^ (row & 7u)) << 4);
}
__device__ __forceinline__ void ldsm4(uint32_t addr, uint32_t* r) {
    asm volatile("ldmatrix.sync.aligned.m8n8.x4.shared.b16 {%0,%1,%2,%3}, [%4];"
                 : "=r"(r[0]), "=r"(r[1]), "=r"(r[2]), "=r"(r[3]) : "r"(addr));
}
__device__ __forceinline__ void mma16816(float* c, const uint32_t* a, const uint32_t* b) {
    asm volatile(
        "mma.sync.aligned.m16n8k16.row.col.f32.f16.f16.f32 "
        "{%0,%1,%2,%3}, {%4,%5,%6,%7}, {%8,%9}, {%0,%1,%2,%3};"
        : "+f"(c[0]), "+f"(c[1]), "+f"(c[2]), "+f"(c[3])
        : "r"(a[0]), "r"(a[1]), "r"(a[2]), "r"(a[3]), "r"(b[0]), "r"(b[1]));
}

// ------------------------- prep kernels -------------------------
__global__ void prep_wsplit(const float* __restrict__ W, const float* __restrict__ mask) {
    size_t t = (size_t)blockIdx.x * blockDim.x + threadIdx.x;
    size_t s = t * 2;
    float2 w  = *(const float2*)(W + s);
    float2 mk = *(const float2*)(mask + s);
    float w0 = w.x * fminf(fmaxf(mk.x, 0.f), 1.f);
    float w1 = w.y * fminf(fmaxf(mk.y, 0.f), 1.f);
    int m = (int)(s & 2047);
    size_t r = s >> 11;
    int n = (int)(r & 2047); r >>= 11;
    int i = (int)(r & 3);
    int o = (int)(r >> 2);
    size_t dst = ((size_t)((o << 11) | n)) * NTOT + ((i << 11) | m);
    __half h0, l0, h1, l1;
    split_h(w0, h0, l0); split_h(w1, h1, l1);
    *(uint32_t*)(g_Whi + dst) = pack2h(h0, h1);
    *(uint32_t*)(g_Wlo + dst) = pack2h(l0, l1);
}
__global__ void prep_rsplit(const float* __restrict__ Rw) {
    size_t s = ((size_t)blockIdx.x * blockDim.x + threadIdx.x) * 2;
    float2 w = *(const float2*)(Rw + s);
    __half h0, l0, h1, l1;
    split_h(w.x, h0, l0); split_h(w.y, h1, l1);
    *(uint32_t*)(g_Rhi + s) = pack2h(h0, h1);
    *(uint32_t*)(g_Rlo + s) = pack2h(l0, l1);
}
__global__ void prep_osplit(const float* __restrict__ Ow, const int* __restrict__ aidx) {
    size_t s = ((size_t)blockIdx.x * blockDim.x + threadIdx.x) * 2;
    int k = (int)(s & 8191);
    int c = (int)(s >> 13);
    float w0 = Ow[(size_t)c * NTOT + aidx[k]];
    float w1 = Ow[(size_t)c * NTOT + aidx[k + 1]];
    __half h0, l0, h1, l1;
    split_h(w0, h0, l0); split_h(w1, h1, l1);
    *(uint32_t*)(g_Ohi + s) = pack2h(h0, h1);
    *(uint32_t*)(g_Olo + s) = pack2h(l0, l1);
}
__global__ void prep_xf(const float* __restrict__ x) {
    size_t s = ((size_t)blockIdx.x * blockDim.x + threadIdx.x) * 2;
    float2 w = *(const float2*)(x + s);
    *(uint32_t*)(g_xf + s) = pack2h(__float2half_rn(w.x), __float2half_rn(w.y));
}
// gates + gated bias. tsum layout: [mtile(2)][ntile(64)]
__global__ void gate_bias_kernel(const float* __restrict__ bb) {
    __shared__ float gsh[A_NUM];
    int t = threadIdx.x;
    if (t < A_NUM) {
        float s = 0.0f;
        for (int mt = 0; mt < 2; mt++)
            for (int nt = t * 16; nt < t * 16 + 16; nt++)
                s += g_tsum[mt * 64 + nt];
        float mean = s * (1.0f / (float)(BATCH * AREA_N));
        float g = (mean > THRESH) ? 1.0f : 0.0f;
        g_gatev[t] = g;
        gsh[t] = g;
    }
    __syncthreads();
    for (int p = t; p < NTOT; p += 256) {
        int o = p >> 11, n = p & 2047;
        float s = 0.0f;
        #pragma unroll
        for (int i = 0; i < A_NUM; i++)
            s += gsh[i] * bb[(o * A_NUM + i) * AREA_N + n];
        g_biasv[p] = s;
    }
}
__global__ void logits_reduce(const float* __restrict__ Ob, float* __restrict__ out) {
    int i = (blockIdx.x * 256 + threadIdx.x) * 4;
    float4 a = *(const float4*)(g_part + i);
    #pragma unroll
    for (int s = 1; s < LOG_SPLIT; s++) {
        float4 b = *(const float4*)(g_part + (size_t)s * LOGITS_ELEMS + i);
        a.x += b.x; a.y += b.y; a.z += b.z; a.w += b.w;
    }
    int n = i & (NCLS - 1);
    float4 ob = *(const float4*)(Ob + n);
    a.x += ob.x; a.y += ob.y; a.z += ob.z; a.w += ob.w;
    *(float4*)(out + i) = a;
}

// ------------------------- stage loader -------------------------
__device__ __forceinline__ void load_tileA(uint32_t sb, const __half* g, int ld, int tid) {
    #pragma unroll
    for (int r = 0; r < 8; r++) {
        int id = tid + r * 256;
        uint32_t row = (uint32_t)id >> 3, c = (uint32_t)id & 7;
        cp16(sb + swz(row, c), g + (size_t)row * ld + c * 8);
    }
}
__device__ __forceinline__ void load_tileB(uint32_t sb, const __half* g, int ld, int tid) {
    #pragma unroll
    for (int r = 0; r < 4; r++) {
        int id = tid + r * 256;
        uint32_t row = (uint32_t)id >> 3, c = (uint32_t)id & 7;
        cp16(sb + swz(row, c), g + (size_t)row * ld + c * 8);
    }
}
__device__ __forceinline__ void load_stage(
    uint32_t sb,
    const __half* Af, const __half* Bhi, const __half* Blo,
    int m0, int n0, int k0, int ld, int tid)
{
    load_tileA(sb,                                Af  + (size_t)m0 * ld + k0, ld, tid);
    load_tileB(sb + A_TILE_BYTES,                 Bhi + (size_t)n0 * ld + k0, ld, tid);
    load_tileB(sb + A_TILE_BYTES + B_TILE_BYTES,  Blo + (size_t)n0 * ld + k0, ld, tid);
    asm volatile("cp.async.commit_group;" ::: "memory");
}

// ------------------------- main GEMM -------------------------
// grid (N/BN, M/BM, zsplit). Warp layout 4(m) x 2(n), warp tile 64x64.
__global__ __launch_bounds__(256, 1)
void god_gemm(const __half* __restrict__ Af,
              const __half* __restrict__ Bhi, const __half* __restrict__ Blo,
              int ldk, int ktiles_in,
              const float* __restrict__ gate,
              const float* __restrict__ bias,
              float* __restrict__ hist,
              float* __restrict__ logits, int logitsN, size_t zstride,
              __half* __restrict__ Zfo,
              float* __restrict__ tsum,
              int do_tanh)
{
    extern __shared__ char dsm[];
    __shared__ float s_wsum[8];

    const int tid  = threadIdx.x;
    const int wid  = tid >> 5, lane = tid & 31;
    const int wm   = wid >> 1;
    const int wn   = wid & 1;
    const int m0   = blockIdx.y * BM;
    const int n0   = blockIdx.x * BN;
    const int k0tile = blockIdx.z * ktiles_in;
    const uint32_t sbase = smem_u32(dsm);
    if (logits) logits += (size_t)blockIdx.z * zstride;

    // active-area map (uniform; area = 32 BK-tiles)
    int aa[A_NUM];
    int nact;
    if (gate) {
        int c = 0;
        #pragma unroll
        for (int a = 0; a < A_NUM; a++)
            if (__ldg(gate + a) != 0.0f) aa[c++] = a;
        nact = c * 32;
    } else {
        nact = ktiles_in;
        aa[0] = 0;
    }
    #define KT(i) (gate ? (aa[(i) >> 5] * 32 + ((i) & 31)) : (k0tile + (i)))

    float acc[4][8][4];
    #pragma unroll
    for (int a = 0; a < 4; a++)
        #pragma unroll
        for (int b = 0; b < 8; b++)
            #pragma unroll
            for (int c = 0; c < 4; c++) acc[a][b][c] = 0.0f;

    const uint32_t a_row = (lane & 7) + ((lane >> 3) & 1) * 8;
    const uint32_t a_ch  = (lane >> 4);
    const uint32_t b_row = (lane & 7) + (lane >> 4) * 8;
    const uint32_t b_ch  = (lane >> 3) & 1;

    if (nact > 0)
        load_stage(sbase, Af, Bhi, Blo, m0, n0, KT(0) * BK, ldk, tid);
    if (nact > 1)
        load_stage(sbase + STAGE_BYTES, Af, Bhi, Blo, m0, n0, KT(1) * BK, ldk, tid);

    int sl = 0;
    #pragma unroll 1
    for (int i = 0; i < nact; i++) {
        if (i + 1 < nact) { asm volatile("cp.async.wait_group 1;" ::: "memory"); }
        else              { asm volatile("cp.async.wait_group 0;" ::: "memory"); }
        __syncthreads();

        if (i + 2 < nact) {
            int s2 = sl + 2; if (s2 >= NSTAGE) s2 -= NSTAGE;
            load_stage(sbase + (uint32_t)s2 * STAGE_BYTES,
                       Af, Bhi, Blo, m0, n0, KT(i + 2) * BK, ldk, tid);
        }

        const uint32_t sb  = sbase + (uint32_t)sl * STAGE_BYTES;
        const uint32_t sA  = sb;
        const uint32_t sB  = sb + A_TILE_BYTES;
        const uint32_t sBl = sb + A_TILE_BYTES + B_TILE_BYTES;

        #pragma unroll
        for (int ks = 0; ks < 4; ks++) {
            uint32_t bh[4][4], bl[4][4];
            #pragma unroll
            for (int ng = 0; ng < 4; ng++) {
                uint32_t row = wn * 64 + ng * 16 + b_row;
                uint32_t off = swz(row, ks * 2 + b_ch);
                ldsm4(sB + off, bh[ng]);
                ldsm4(sBl + off, bl[ng]);
            }
            #pragma unroll
            for (int mt = 0; mt < 4; mt++) {
                uint32_t ah[4];
                uint32_t row = wm * 64 + mt * 16 + a_row;
                uint32_t off = swz(row, ks * 2 + a_ch);
                ldsm4(sA + off, ah);
                #pragma unroll
                for (int nt = 0; nt < 8; nt++) {
                    mma16816(acc[mt][nt], ah, bh[nt >> 1] + (nt & 1) * 2);
                    mma16816(acc[mt][nt], ah, bl[nt >> 1] + (nt & 1) * 2);
                }
            }
        }
        sl++; if (sl == NSTAGE) sl = 0;
    }

    // ---- epilogue ----
    float asum = 0.0f;
    const int lrow = lane >> 2;
    const int lcol = (lane & 3) * 2;
    #pragma unroll
    for (int mt = 0; mt < 4; mt++) {
        #pragma unroll
        for (int half = 0; half < 2; half++) {
            const int m = m0 + wm * 64 + mt * 16 + lrow + half * 8;
            #pragma unroll
            for (int nt = 0; nt < 8; nt++) {
                const int n = n0 + wn * 64 + nt * 8 + lcol;
                float v0 = acc[mt][nt][half * 2 + 0] + (bias ? __ldg(bias + n) : 0.0f);
                float v1 = acc[mt][nt][half * 2 + 1] + (bias ? __ldg(bias + n + 1) : 0.0f);
                if (do_tanh) { v0 = tanhf(v0); v1 = tanhf(v1); }
                asum += fabsf(v0) + fabsf(v1);
                if (hist) {
                    int a = n >> 11, nn = n & 2047;
                    *(float2*)(hist + ((size_t)a * BATCH + m) * AREA_N + nn) =
                        make_float2(v0, v1);
                }
                if (logits)
                    *(float2*)(logits + (size_t)m * logitsN + n) = make_float2(v0, v1);
                if (Zfo)
                    *(uint32_t*)(Zfo + (size_t)m * NTOT + n) =
                        pack2h(__float2half_rn(v0), __float2half_rn(v1));
            }
        }
    }

    if (tsum) {
        #pragma unroll
        for (int o = 16; o; o >>= 1) asum += __shfl_xor_sync(0xffffffffu, asum, o);
        if (lane == 0) s_wsum[wid] = asum;
        __syncthreads();
        if (tid == 0) {
            float s = ((s_wsum[0] + s_wsum[1]) + (s_wsum[2] + s_wsum[3]))
                    + ((s_wsum[4] + s_wsum[5]) + (s_wsum[6] + s_wsum[7]));
            tsum[blockIdx.y * 64 + blockIdx.x] = s;
        }
    }
}

// ------------------------- launch -------------------------
extern "C" void kernel_launch(void* const* d_in, const int* in_sizes, int n_in,
                              void* d_out, int out_size) {
    const float* x    = (const float*)d_in[0];
    const float* Rw   = (const float*)d_in[1];
    const float* rb   = (const float*)d_in[2];
    const float* Wb   = (const float*)d_in[3];
    const float* bb   = (const float*)d_in[4];
    const float* mask = (const float*)d_in[5];
    const float* Ow   = (const float*)d_in[6];
    const float* Ob   = (const float*)d_in[7];
    const int*   aidx = (const int*)d_in[8];

    float* out  = (float*)d_out;
    float* hist = out + LOGITS_ELEMS;

    __half *whi, *wlo, *rhi, *rlo, *ohi, *olo, *xf, *zf[2];
    float *tsum, *gatev, *biasv, *part;
    cudaGetSymbolAddress((void**)&whi, g_Whi);
    cudaGetSymbolAddress((void**)&wlo, g_Wlo);
    cudaGetSymbolAddress((void**)&rhi, g_Rhi);
    cudaGetSymbolAddress((void**)&rlo, g_Rlo);
    cudaGetSymbolAddress((void**)&ohi, g_Ohi);
    cudaGetSymbolAddress((void**)&olo, g_Olo);
    cudaGetSymbolAddress((void**)&xf,  g_xf);
    cudaGetSymbolAddress((void**)&zf[0], g_Zf0);
    cudaGetSymbolAddress((void**)&zf[1], g_Zf1);
    cudaGetSymbolAddress((void**)&tsum,  g_tsum);
    cudaGetSymbolAddress((void**)&gatev, g_gatev);
    cudaGetSymbolAddress((void**)&biasv, g_biasv);
    cudaGetSymbolAddress((void**)&part,  g_part);

    cudaFuncSetAttribute(god_gemm, cudaFuncAttributeMaxDynamicSharedMemorySize, SMEM_DYN);

    // prep (ordered so the encode GEMM is the 4th launch for ncu capture)
    prep_xf<<<1024, 256>>>(x);
    prep_rsplit<<<16384, 256>>>(Rw);
    prep_osplit<<<16384, 256>>>(Ow, aidx);

    // encode (K=1024): Z0 = tanh(x @ Rw^T + rb), writes history[0] + tsum
    god_gemm<<<dim3(64, 2), 256, SMEM_DYN>>>(
        xf, rhi, rlo, D_INPUT, D_INPUT / BK,
        nullptr, rb, hist, nullptr, 0, 0,
        zf[0], tsum, 1);

    // W prep (only needed before tick 1)
    prep_wsplit<<<131072, 256>>>(Wb, mask);

    // ticks (K=8192, area-gated)
    int p = 0;
    for (int t = 0; t < NTICKS; t++) {
        gate_bias_kernel<<<1, 256>>>(bb);
        god_gemm<<<dim3(64, 2), 256, SMEM_DYN>>>(
            zf[p], whi, wlo, NTOT, 0,
            gatev, biasv, hist + (size_t)(t + 1) * HIST_STEP, nullptr, 0, 0,
            zf[1 - p], tsum, 1);
        p ^= 1;
    }

    // logits: one 3D launch, 8-way split-K, then deterministic reduce (+Ob)
    god_gemm<<<dim3(8, 2, LOG_SPLIT), 256, SMEM_DYN>>>(
        zf[p], ohi, olo, NTOT, LOG_KTILES,
        nullptr, nullptr, nullptr, part, NCLS, (size_t)LOGITS_ELEMS,
        nullptr, nullptr, 0);
    logits_reduce<<<LOGITS_ELEMS / 1024, 256>>>(Ob, out);
}

// round 8
// speedup vs baseline: 7.6177x; 1.4742x over previous
#include <cuda_runtime.h>
#include <cuda_fp16.h>
#include <math.h>
#include <stdint.h>

// ---------------------------------------------------------------------------
// GodAreaModel via mma.sync fp16.
// Ticks/logits: single-term fp16 (C = Z*Whi).  Encode: 2-term (x*Rhi + x*Rlo).
// Error budget: ~u/sqrt(3) per fp16-rounded operand; total ~5e-4 < 1e-3 gate.
// ---------------------------------------------------------------------------

#define A_NUM   4
#define AREA_N  2048
#define NTOT    8192
#define D_INPUT 1024
#define NCLS    1024
#define BATCH   512
#define NTICKS  4
#define THRESH  0.05f
#define LOGITS_ELEMS (BATCH * NCLS)
#define HIST_STEP    (A_NUM * BATCH * AREA_N)

// Block tile
#define BM 256
#define BN 128
#define BK 64
#define A_TILE_BYTES (BM * BK * 2)          // 32768
#define B_TILE_BYTES (BN * BK * 2)          // 16384
#define SMEM_MAX 196608                     // 192KB both variants

#define LOG_SPLIT 8
#define LOG_KTILES (NTOT / BK / LOG_SPLIT)  // 16

// ------------------------- device scratch -------------------------
__device__ __align__(256) __half g_Whi[(size_t)NTOT * NTOT];
__device__ __align__(256) __half g_Rhi[(size_t)NTOT * D_INPUT];
__device__ __align__(256) __half g_Rlo[(size_t)NTOT * D_INPUT];
__device__ __align__(256) __half g_Ohi[(size_t)NCLS * NTOT];
__device__ __align__(256) __half g_xf [(size_t)BATCH * D_INPUT];
__device__ __align__(256) __half g_Zf0[(size_t)BATCH * NTOT];
__device__ __align__(256) __half g_Zf1[(size_t)BATCH * NTOT];
__device__ __align__(256) float g_part[(size_t)LOG_SPLIT * LOGITS_ELEMS];
__device__ __align__(256) float g_tsum[256];
__device__ __align__(256) float g_gatev[A_NUM];
__device__ __align__(256) float g_biasv[NTOT];

// ------------------------- helpers -------------------------
__device__ __forceinline__ uint32_t smem_u32(const void* p) {
    return (uint32_t)__cvta_generic_to_shared(p);
}
__device__ __forceinline__ uint32_t pack2h(__half a, __half b) {
    __half2 v; v.x = a; v.y = b;
    return *reinterpret_cast<uint32_t*>(&v);
}
__device__ __forceinline__ void split_h(float w, __half& h, __half& l) {
    h = __float2half_rn(w);
    l = __float2half_rn(w - __half2float(h));
}
__device__ __forceinline__ void cp16(uint32_t saddr, const void* g) {
    asm volatile("cp.async.cg.shared.global [%0], [%1], 16;" :: "r"(saddr), "l"(g));
}
template<int N>
__device__ __forceinline__ void cp_wait() {
    asm volatile("cp.async.wait_group %0;" :: "n"(N) : "memory");
}
// swizzled byte offset within a [rows x 64] fp16 tile (rows of 128B, 8x16B chunks)
__device__ __forceinline__ uint32_t swz(uint32_t row, uint32_t chunk) {
    return row * 128u + ((chunk ^ (row & 7u)) << 4);
}
__device__ __forceinline__ void ldsm4(uint32_t addr, uint32_t* r) {
    asm volatile("ldmatrix.sync.aligned.m8n8.x4.shared.b16 {%0,%1,%2,%3}, [%4];"
                 : "=r"(r[0]), "=r"(r[1]), "=r"(r[2]), "=r"(r[3]) : "r"(addr));
}
__device__ __forceinline__ void mma16816(float* c, const uint32_t* a, const uint32_t* b) {
    asm volatile(
        "mma.sync.aligned.m16n8k16.row.col.f32.f16.f16.f32 "
        "{%0,%1,%2,%3}, {%4,%5,%6,%7}, {%8,%9}, {%0,%1,%2,%3};"
        : "+f"(c[0]), "+f"(c[1]), "+f"(c[2]), "+f"(c[3])
        : "r"(a[0]), "r"(a[1]), "r"(a[2]), "r"(a[3]), "r"(b[0]), "r"(b[1]));
}

// ------------------------- prep kernels -------------------------
__global__ void prep_wsplit(const float* __restrict__ W, const float* __restrict__ mask) {
    size_t t = (size_t)blockIdx.x * blockDim.x + threadIdx.x;
    size_t s = t * 2;
    float2 w  = *(const float2*)(W + s);
    float2 mk = *(const float2*)(mask + s);
    float w0 = w.x * fminf(fmaxf(mk.x, 0.f), 1.f);
    float w1 = w.y * fminf(fmaxf(mk.y, 0.f), 1.f);
    int m = (int)(s & 2047);
    size_t r = s >> 11;
    int n = (int)(r & 2047); r >>= 11;
    int i = (int)(r & 3);
    int o = (int)(r >> 2);
    size_t dst = ((size_t)((o << 11) | n)) * NTOT + ((i << 11) | m);
    *(uint32_t*)(g_Whi + dst) = pack2h(__float2half_rn(w0), __float2half_rn(w1));
}
__global__ void prep_rsplit(const float* __restrict__ Rw) {
    size_t s = ((size_t)blockIdx.x * blockDim.x + threadIdx.x) * 2;
    float2 w = *(const float2*)(Rw + s);
    __half h0, l0, h1, l1;
    split_h(w.x, h0, l0); split_h(w.y, h1, l1);
    *(uint32_t*)(g_Rhi + s) = pack2h(h0, h1);
    *(uint32_t*)(g_Rlo + s) = pack2h(l0, l1);
}
__global__ void prep_osplit(const float* __restrict__ Ow, const int* __restrict__ aidx) {
    size_t s = ((size_t)blockIdx.x * blockDim.x + threadIdx.x) * 2;
    int k = (int)(s & 8191);
    int c = (int)(s >> 13);
    float w0 = Ow[(size_t)c * NTOT + aidx[k]];
    float w1 = Ow[(size_t)c * NTOT + aidx[k + 1]];
    *(uint32_t*)(g_Ohi + s) = pack2h(__float2half_rn(w0), __float2half_rn(w1));
}
__global__ void prep_xf(const float* __restrict__ x) {
    size_t s = ((size_t)blockIdx.x * blockDim.x + threadIdx.x) * 2;
    float2 w = *(const float2*)(x + s);
    *(uint32_t*)(g_xf + s) = pack2h(__float2half_rn(w.x), __float2half_rn(w.y));
}
// gates + gated bias. tsum layout: [mtile(2)][ntile(64)]
__global__ void gate_bias_kernel(const float* __restrict__ bb) {
    __shared__ float gsh[A_NUM];
    int t = threadIdx.x;
    if (t < A_NUM) {
        float s = 0.0f;
        for (int mt = 0; mt < 2; mt++)
            for (int nt = t * 16; nt < t * 16 + 16; nt++)
                s += g_tsum[mt * 64 + nt];
        float mean = s * (1.0f / (float)(BATCH * AREA_N));
        float g = (mean > THRESH) ? 1.0f : 0.0f;
        g_gatev[t] = g;
        gsh[t] = g;
    }
    __syncthreads();
    for (int p = t; p < NTOT; p += 256) {
        int o = p >> 11, n = p & 2047;
        float s = 0.0f;
        #pragma unroll
        for (int i = 0; i < A_NUM; i++)
            s += gsh[i] * bb[(o * A_NUM + i) * AREA_N + n];
        g_biasv[p] = s;
    }
}
__global__ void logits_reduce(const float* __restrict__ Ob, float* __restrict__ out) {
    int i = (blockIdx.x * 256 + threadIdx.x) * 4;
    float4 a = *(const float4*)(g_part + i);
    #pragma unroll
    for (int s = 1; s < LOG_SPLIT; s++) {
        float4 b = *(const float4*)(g_part + (size_t)s * LOGITS_ELEMS + i);
        a.x += b.x; a.y += b.y; a.z += b.z; a.w += b.w;
    }
    int n = i & (NCLS - 1);
    float4 ob = *(const float4*)(Ob + n);
    a.x += ob.x; a.y += ob.y; a.z += ob.z; a.w += ob.w;
    *(float4*)(out + i) = a;
}

// ------------------------- stage loader -------------------------
__device__ __forceinline__ void load_tileA(uint32_t sb, const __half* g, int ld, int tid) {
    #pragma unroll
    for (int r = 0; r < 8; r++) {
        int id = tid + r * 256;
        uint32_t row = (uint32_t)id >> 3, c = (uint32_t)id & 7;
        cp16(sb + swz(row, c), g + (size_t)row * ld + c * 8);
    }
}
__device__ __forceinline__ void load_tileB(uint32_t sb, const __half* g, int ld, int tid) {
    #pragma unroll
    for (int r = 0; r < 4; r++) {
        int id = tid + r * 256;
        uint32_t row = (uint32_t)id >> 3, c = (uint32_t)id & 7;
        cp16(sb + swz(row, c), g + (size_t)row * ld + c * 8);
    }
}
template<int TERMS>
__device__ __forceinline__ void load_stage(
    uint32_t sb,
    const __half* Af, const __half* Bhi, const __half* Blo,
    int m0, int n0, int k0, int ld, int tid)
{
    load_tileA(sb,                Af  + (size_t)m0 * ld + k0, ld, tid);
    load_tileB(sb + A_TILE_BYTES, Bhi + (size_t)n0 * ld + k0, ld, tid);
    if (TERMS == 2)
        load_tileB(sb + A_TILE_BYTES + B_TILE_BYTES, Blo + (size_t)n0 * ld + k0, ld, tid);
    asm volatile("cp.async.commit_group;" ::: "memory");
}

// ------------------------- main GEMM -------------------------
// grid (N/BN, M/BM, zsplit). Warp layout 4(m) x 2(n), warp tile 64x64.
template<int TERMS>
__global__ __launch_bounds__(256, 1)
void god_gemm(const __half* __restrict__ Af,
              const __half* __restrict__ Bhi, const __half* __restrict__ Blo,
              int ldk, int ktiles_in,
              const float* __restrict__ gate,
              const float* __restrict__ bias,
              float* __restrict__ hist,
              float* __restrict__ logits, int logitsN, size_t zstride,
              __half* __restrict__ Zfo,
              float* __restrict__ tsum,
              int do_tanh)
{
    constexpr int ST  = A_TILE_BYTES + TERMS * B_TILE_BYTES;  // 48K or 64K
    constexpr int NST = (TERMS == 1) ? 4 : 3;

    extern __shared__ char dsm[];
    __shared__ float s_wsum[8];

    const int tid  = threadIdx.x;
    const int wid  = tid >> 5, lane = tid & 31;
    const int wm   = wid >> 1;
    const int wn   = wid & 1;
    const int m0   = blockIdx.y * BM;
    const int n0   = blockIdx.x * BN;
    const int k0tile = blockIdx.z * ktiles_in;
    const uint32_t sbase = smem_u32(dsm);
    if (logits) logits += (size_t)blockIdx.z * zstride;

    // active-area map (uniform; area = 32 BK-tiles)
    int aa[A_NUM];
    int nact;
    if (gate) {
        int c = 0;
        #pragma unroll
        for (int a = 0; a < A_NUM; a++)
            if (__ldg(gate + a) != 0.0f) aa[c++] = a;
        nact = c * 32;
    } else {
        nact = ktiles_in;
        aa[0] = 0;
    }
    #define KT(i) (gate ? (aa[(i) >> 5] * 32 + ((i) & 31)) : (k0tile + (i)))

    float acc[4][8][4];
    #pragma unroll
    for (int a = 0; a < 4; a++)
        #pragma unroll
        for (int b = 0; b < 8; b++)
            #pragma unroll
            for (int c = 0; c < 4; c++) acc[a][b][c] = 0.0f;

    const uint32_t a_row = (lane & 7) + ((lane >> 3) & 1) * 8;
    const uint32_t a_ch  = (lane >> 4);
    const uint32_t b_row = (lane & 7) + (lane >> 4) * 8;
    const uint32_t b_ch  = (lane >> 3) & 1;

    #pragma unroll
    for (int s = 0; s < NST - 1; s++)
        if (s < nact)
            load_stage<TERMS>(sbase + (uint32_t)s * ST, Af, Bhi, Blo,
                              m0, n0, KT(s) * BK, ldk, tid);

    int sl = 0;
    #pragma unroll 1
    for (int i = 0; i < nact; i++) {
        int rem = nact - i - 1;
        if (rem >= NST - 2)           cp_wait<NST - 2>();
        else if (NST == 4 && rem == 1) cp_wait<1>();
        else                           cp_wait<0>();
        __syncthreads();

        if (i + NST - 1 < nact) {
            int s2 = sl + NST - 1; if (s2 >= NST) s2 -= NST;
            load_stage<TERMS>(sbase + (uint32_t)s2 * ST, Af, Bhi, Blo,
                              m0, n0, KT(i + NST - 1) * BK, ldk, tid);
        }

        const uint32_t sb  = sbase + (uint32_t)sl * ST;
        const uint32_t sA  = sb;
        const uint32_t sB  = sb + A_TILE_BYTES;
        const uint32_t sBl = sb + A_TILE_BYTES + B_TILE_BYTES;

        #pragma unroll
        for (int ks = 0; ks < 4; ks++) {
            uint32_t bh[4][4], bl[4][4];
            #pragma unroll
            for (int ng = 0; ng < 4; ng++) {
                uint32_t row = wn * 64 + ng * 16 + b_row;
                uint32_t off = swz(row, ks * 2 + b_ch);
                ldsm4(sB + off, bh[ng]);
                if (TERMS == 2) ldsm4(sBl + off, bl[ng]);
            }
            #pragma unroll
            for (int mt = 0; mt < 4; mt++) {
                uint32_t ah[4];
                uint32_t row = wm * 64 + mt * 16 + a_row;
                uint32_t off = swz(row, ks * 2 + a_ch);
                ldsm4(sA + off, ah);
                #pragma unroll
                for (int nt = 0; nt < 8; nt++) {
                    mma16816(acc[mt][nt], ah, bh[nt >> 1] + (nt & 1) * 2);
                    if (TERMS == 2)
                        mma16816(acc[mt][nt], ah, bl[nt >> 1] + (nt & 1) * 2);
                }
            }
        }
        sl++; if (sl == NST) sl = 0;
    }

    // ---- epilogue ----
    float asum = 0.0f;
    const int lrow = lane >> 2;
    const int lcol = (lane & 3) * 2;
    #pragma unroll
    for (int mt = 0; mt < 4; mt++) {
        #pragma unroll
        for (int half = 0; half < 2; half++) {
            const int m = m0 + wm * 64 + mt * 16 + lrow + half * 8;
            #pragma unroll
            for (int nt = 0; nt < 8; nt++) {
                const int n = n0 + wn * 64 + nt * 8 + lcol;
                float v0 = acc[mt][nt][half * 2 + 0] + (bias ? __ldg(bias + n) : 0.0f);
                float v1 = acc[mt][nt][half * 2 + 1] + (bias ? __ldg(bias + n + 1) : 0.0f);
                if (do_tanh) { v0 = tanhf(v0); v1 = tanhf(v1); }
                asum += fabsf(v0) + fabsf(v1);
                if (hist) {
                    int a = n >> 11, nn = n & 2047;
                    *(float2*)(hist + ((size_t)a * BATCH + m) * AREA_N + nn) =
                        make_float2(v0, v1);
                }
                if (logits)
                    *(float2*)(logits + (size_t)m * logitsN + n) = make_float2(v0, v1);
                if (Zfo)
                    *(uint32_t*)(Zfo + (size_t)m * NTOT + n) =
                        pack2h(__float2half_rn(v0), __float2half_rn(v1));
            }
        }
    }

    if (tsum) {
        #pragma unroll
        for (int o = 16; o; o >>= 1) asum += __shfl_xor_sync(0xffffffffu, asum, o);
        if (lane == 0) s_wsum[wid] = asum;
        __syncthreads();
        if (tid == 0) {
            float s = ((s_wsum[0] + s_wsum[1]) + (s_wsum[2] + s_wsum[3]))
                    + ((s_wsum[4] + s_wsum[5]) + (s_wsum[6] + s_wsum[7]));
            tsum[blockIdx.y * 64 + blockIdx.x] = s;
        }
    }
}

// ------------------------- launch -------------------------
extern "C" void kernel_launch(void* const* d_in, const int* in_sizes, int n_in,
                              void* d_out, int out_size) {
    const float* x    = (const float*)d_in[0];
    const float* Rw   = (const float*)d_in[1];
    const float* rb   = (const float*)d_in[2];
    const float* Wb   = (const float*)d_in[3];
    const float* bb   = (const float*)d_in[4];
    const float* mask = (const float*)d_in[5];
    const float* Ow   = (const float*)d_in[6];
    const float* Ob   = (const float*)d_in[7];
    const int*   aidx = (const int*)d_in[8];

    float* out  = (float*)d_out;
    float* hist = out + LOGITS_ELEMS;

    __half *whi, *rhi, *rlo, *ohi, *xf, *zf[2];
    float *tsum, *gatev, *biasv, *part;
    cudaGetSymbolAddress((void**)&whi, g_Whi);
    cudaGetSymbolAddress((void**)&rhi, g_Rhi);
    cudaGetSymbolAddress((void**)&rlo, g_Rlo);
    cudaGetSymbolAddress((void**)&ohi, g_Ohi);
    cudaGetSymbolAddress((void**)&xf,  g_xf);
    cudaGetSymbolAddress((void**)&zf[0], g_Zf0);
    cudaGetSymbolAddress((void**)&zf[1], g_Zf1);
    cudaGetSymbolAddress((void**)&tsum,  g_tsum);
    cudaGetSymbolAddress((void**)&gatev, g_gatev);
    cudaGetSymbolAddress((void**)&biasv, g_biasv);
    cudaGetSymbolAddress((void**)&part,  g_part);

    cudaFuncSetAttribute(god_gemm<1>, cudaFuncAttributeMaxDynamicSharedMemorySize, SMEM_MAX);
    cudaFuncSetAttribute(god_gemm<2>, cudaFuncAttributeMaxDynamicSharedMemorySize, SMEM_MAX);

    // prep
    prep_xf<<<1024, 256>>>(x);
    prep_rsplit<<<16384, 256>>>(Rw);
    prep_osplit<<<16384, 256>>>(Ow, aidx);

    // encode (K=1024, 2-term): Z0 = tanh(x @ Rw^T + rb)
    god_gemm<2><<<dim3(64, 2), 256, SMEM_MAX>>>(
        xf, rhi, rlo, D_INPUT, D_INPUT / BK,
        nullptr, rb, hist, nullptr, 0, 0,
        zf[0], tsum, 1);

    // W prep (needed before tick 1)
    prep_wsplit<<<131072, 256>>>(Wb, mask);

    // ticks (K=8192, area-gated, 1-term)
    int p = 0;
    for (int t = 0; t < NTICKS; t++) {
        gate_bias_kernel<<<1, 256>>>(bb);
        god_gemm<1><<<dim3(64, 2), 256, SMEM_MAX>>>(
            zf[p], whi, nullptr, NTOT, 0,
            gatev, biasv, hist + (size_t)(t + 1) * HIST_STEP, nullptr, 0, 0,
            zf[1 - p], tsum, 1);
        p ^= 1;
    }

    // logits (1-term): one 3D launch, 8-way split-K, then reduce (+Ob)
    god_gemm<1><<<dim3(8, 2, LOG_SPLIT), 256, SMEM_MAX>>>(
        zf[p], ohi, nullptr, NTOT, LOG_KTILES,
        nullptr, nullptr, nullptr, part, NCLS, (size_t)LOGITS_ELEMS,
        nullptr, nullptr, 0);
    logits_reduce<<<LOGITS_ELEMS / 1024, 256>>>(Ob, out);
}

// round 9
// speedup vs baseline: 7.9852x; 1.0482x over previous
#include <cuda_runtime.h>
#include <cuda_fp16.h>
#include <math.h>
#include <stdint.h>

// ---------------------------------------------------------------------------
// GodAreaModel via mma.sync fp16, single-term everywhere (C = A*Bhi).
// Error model (calibrated R6/R7): each fp16-rounded operand adds ~u/sqrt(3)
// rms in quadrature, contracted by tanh; total ~3e-4 << 1e-3 gate.
// ---------------------------------------------------------------------------

#define A_NUM   4
#define AREA_N  2048
#define NTOT    8192
#define D_INPUT 1024
#define NCLS    1024
#define BATCH   512
#define NTICKS  4
#define THRESH  0.05f
#define LOGITS_ELEMS (BATCH * NCLS)
#define HIST_STEP    (A_NUM * BATCH * AREA_N)

// Block tile
#define BM 256
#define BN 128
#define BK 64
#define A_TILE_BYTES (BM * BK * 2)          // 32768
#define B_TILE_BYTES (BN * BK * 2)          // 16384
#define ST_BYTES (A_TILE_BYTES + B_TILE_BYTES)  // 49152
#define NST 4
#define SMEM_DYN (NST * ST_BYTES)           // 196608

#define LOG_SPLIT 8
#define LOG_KTILES (NTOT / BK / LOG_SPLIT)  // 16

// ------------------------- device scratch -------------------------
__device__ __align__(256) __half g_Whi[(size_t)NTOT * NTOT];
__device__ __align__(256) __half g_Rhi[(size_t)NTOT * D_INPUT];
__device__ __align__(256) __half g_Ohi[(size_t)NCLS * NTOT];
__device__ __align__(256) __half g_xf [(size_t)BATCH * D_INPUT];
__device__ __align__(256) __half g_Zf0[(size_t)BATCH * NTOT];
__device__ __align__(256) __half g_Zf1[(size_t)BATCH * NTOT];
__device__ __align__(256) float g_part[(size_t)LOG_SPLIT * LOGITS_ELEMS];
__device__ __align__(256) float g_tsum[256];
__device__ __align__(256) float g_gatev[A_NUM];
__device__ __align__(256) float g_biasv[NTOT];

// ------------------------- helpers -------------------------
__device__ __forceinline__ uint32_t smem_u32(const void* p) {
    return (uint32_t)__cvta_generic_to_shared(p);
}
__device__ __forceinline__ uint32_t pack2h(__half a, __half b) {
    __half2 v; v.x = a; v.y = b;
    return *reinterpret_cast<uint32_t*>(&v);
}
__device__ __forceinline__ void cp16(uint32_t saddr, const void* g) {
    asm volatile("cp.async.cg.shared.global [%0], [%1], 16;" :: "r"(saddr), "l"(g));
}
template<int N>
__device__ __forceinline__ void cp_wait() {
    asm volatile("cp.async.wait_group %0;" :: "n"(N) : "memory");
}
__device__ __forceinline__ uint32_t swz(uint32_t row, uint32_t chunk) {
    return row * 128u + ((chunk ^ (row & 7u)) << 4);
}
__device__ __forceinline__ void ldsm4(uint32_t addr, uint32_t* r) {
    asm volatile("ldmatrix.sync.aligned.m8n8.x4.shared.b16 {%0,%1,%2,%3}, [%4];"
                 : "=r"(r[0]), "=r"(r[1]), "=r"(r[2]), "=r"(r[3]) : "r"(addr));
}
__device__ __forceinline__ void mma16816(float* c, const uint32_t* a, const uint32_t* b) {
    asm volatile(
        "mma.sync.aligned.m16n8k16.row.col.f32.f16.f16.f32 "
        "{%0,%1,%2,%3}, {%4,%5,%6,%7}, {%8,%9}, {%0,%1,%2,%3};"
        : "+f"(c[0]), "+f"(c[1]), "+f"(c[2]), "+f"(c[3])
        : "r"(a[0]), "r"(a[1]), "r"(a[2]), "r"(a[3]), "r"(b[0]), "r"(b[1]));
}

// ------------------------- prep kernels -------------------------
// Streaming float4 version: 512 MB read + 64 MB write, grid-stride.
__global__ void prep_wsplit(const float4* __restrict__ W, const float4* __restrict__ mask) {
    const size_t total = (size_t)NTOT * NTOT / 4;   // 16M float4
    const size_t stride = (size_t)gridDim.x * blockDim.x;
    for (size_t q = (size_t)blockIdx.x * blockDim.x + threadIdx.x; q < total; q += stride) {
        float4 w  = W[q];
        float4 mk = mask[q];
        float v0 = w.x * fminf(fmaxf(mk.x, 0.f), 1.f);
        float v1 = w.y * fminf(fmaxf(mk.y, 0.f), 1.f);
        float v2 = w.z * fminf(fmaxf(mk.z, 0.f), 1.f);
        float v3 = w.w * fminf(fmaxf(mk.w, 0.f), 1.f);
        size_t s = q * 4;
        int m = (int)(s & 2047);
        size_t r = s >> 11;
        int n = (int)(r & 2047); r >>= 11;
        int i = (int)(r & 3);
        int o = (int)(r >> 2);
        size_t dst = ((size_t)((o << 11) | n)) * NTOT + ((i << 11) | m);
        uint2 out;
        out.x = pack2h(__float2half_rn(v0), __float2half_rn(v1));
        out.y = pack2h(__float2half_rn(v2), __float2half_rn(v3));
        *(uint2*)(g_Whi + dst) = out;
    }
}
__global__ void prep_rhalf(const float4* __restrict__ Rw) {
    const size_t total = (size_t)NTOT * D_INPUT / 4;
    const size_t stride = (size_t)gridDim.x * blockDim.x;
    for (size_t q = (size_t)blockIdx.x * blockDim.x + threadIdx.x; q < total; q += stride) {
        float4 w = Rw[q];
        uint2 out;
        out.x = pack2h(__float2half_rn(w.x), __float2half_rn(w.y));
        out.y = pack2h(__float2half_rn(w.z), __float2half_rn(w.w));
        *(uint2*)(g_Rhi + q * 4) = out;
    }
}
__global__ void prep_ohalf(const float* __restrict__ Ow, const int* __restrict__ aidx) {
    size_t s = ((size_t)blockIdx.x * blockDim.x + threadIdx.x) * 2;
    int k = (int)(s & 8191);
    int c = (int)(s >> 13);
    float w0 = Ow[(size_t)c * NTOT + aidx[k]];
    float w1 = Ow[(size_t)c * NTOT + aidx[k + 1]];
    *(uint32_t*)(g_Ohi + s) = pack2h(__float2half_rn(w0), __float2half_rn(w1));
}
__global__ void prep_xf(const float* __restrict__ x) {
    size_t s = ((size_t)blockIdx.x * blockDim.x + threadIdx.x) * 2;
    float2 w = *(const float2*)(x + s);
    *(uint32_t*)(g_xf + s) = pack2h(__float2half_rn(w.x), __float2half_rn(w.y));
}
// gates + gated bias. tsum layout: [mtile(2)][ntile(64)]
__global__ void gate_bias_kernel(const float* __restrict__ bb) {
    __shared__ float gsh[A_NUM];
    int t = threadIdx.x;
    if (t < A_NUM) {
        float s = 0.0f;
        for (int mt = 0; mt < 2; mt++)
            for (int nt = t * 16; nt < t * 16 + 16; nt++)
                s += g_tsum[mt * 64 + nt];
        float mean = s * (1.0f / (float)(BATCH * AREA_N));
        float g = (mean > THRESH) ? 1.0f : 0.0f;
        g_gatev[t] = g;
        gsh[t] = g;
    }
    __syncthreads();
    for (int p = t; p < NTOT; p += 256) {
        int o = p >> 11, n = p & 2047;
        float s = 0.0f;
        #pragma unroll
        for (int i = 0; i < A_NUM; i++)
            s += gsh[i] * bb[(o * A_NUM + i) * AREA_N + n];
        g_biasv[p] = s;
    }
}
__global__ void logits_reduce(const float* __restrict__ Ob, float* __restrict__ out) {
    int i = (blockIdx.x * 256 + threadIdx.x) * 4;
    float4 a = *(const float4*)(g_part + i);
    #pragma unroll
    for (int s = 1; s < LOG_SPLIT; s++) {
        float4 b = *(const float4*)(g_part + (size_t)s * LOGITS_ELEMS + i);
        a.x += b.x; a.y += b.y; a.z += b.z; a.w += b.w;
    }
    int n = i & (NCLS - 1);
    float4 ob = *(const float4*)(Ob + n);
    a.x += ob.x; a.y += ob.y; a.z += ob.z; a.w += ob.w;
    *(float4*)(out + i) = a;
}

// ------------------------- stage loader -------------------------
__device__ __forceinline__ void load_tileA(uint32_t sb, const __half* g, int ld, int tid) {
    #pragma unroll
    for (int r = 0; r < 8; r++) {
        int id = tid + r * 256;
        uint32_t row = (uint32_t)id >> 3, c = (uint32_t)id & 7;
        cp16(sb + swz(row, c), g + (size_t)row * ld + c * 8);
    }
}
__device__ __forceinline__ void load_tileB(uint32_t sb, const __half* g, int ld, int tid) {
    #pragma unroll
    for (int r = 0; r < 4; r++) {
        int id = tid + r * 256;
        uint32_t row = (uint32_t)id >> 3, c = (uint32_t)id & 7;
        cp16(sb + swz(row, c), g + (size_t)row * ld + c * 8);
    }
}
__device__ __forceinline__ void load_stage(
    uint32_t sb, const __half* Af, const __half* Bh,
    int m0, int n0, int k0, int ld, int tid)
{
    load_tileA(sb,                Af + (size_t)m0 * ld + k0, ld, tid);
    load_tileB(sb + A_TILE_BYTES, Bh + (size_t)n0 * ld + k0, ld, tid);
    asm volatile("cp.async.commit_group;" ::: "memory");
}

// ------------------------- main GEMM -------------------------
// grid (N/BN, M/BM, zsplit). Warp layout 4(m) x 2(n), warp tile 64x64.
__global__ __launch_bounds__(256, 1)
void god_gemm(const __half* __restrict__ Af, const __half* __restrict__ Bh,
              int ldk, int ktiles_in,
              const float* __restrict__ gate,
              const float* __restrict__ bias,
              float* __restrict__ hist,
              float* __restrict__ logits, int logitsN, size_t zstride,
              __half* __restrict__ Zfo,
              float* __restrict__ tsum,
              int do_tanh)
{
    extern __shared__ char dsm[];
    __shared__ float s_wsum[8];

    const int tid  = threadIdx.x;
    const int wid  = tid >> 5, lane = tid & 31;
    const int wm   = wid >> 1;
    const int wn   = wid & 1;
    const int m0   = blockIdx.y * BM;
    const int n0   = blockIdx.x * BN;
    const int k0tile = blockIdx.z * ktiles_in;
    const uint32_t sbase = smem_u32(dsm);
    if (logits) logits += (size_t)blockIdx.z * zstride;

    // active-area map (uniform; area = 32 BK-tiles)
    int aa[A_NUM];
    int nact;
    if (gate) {
        int c = 0;
        #pragma unroll
        for (int a = 0; a < A_NUM; a++)
            if (__ldg(gate + a) != 0.0f) aa[c++] = a;
        nact = c * 32;
    } else {
        nact = ktiles_in;
        aa[0] = 0;
    }
    #define KT(i) (gate ? (aa[(i) >> 5] * 32 + ((i) & 31)) : (k0tile + (i)))

    float acc[4][8][4];
    #pragma unroll
    for (int a = 0; a < 4; a++)
        #pragma unroll
        for (int b = 0; b < 8; b++)
            #pragma unroll
            for (int c = 0; c < 4; c++) acc[a][b][c] = 0.0f;

    const uint32_t a_row = (lane & 7) + ((lane >> 3) & 1) * 8;
    const uint32_t a_ch  = (lane >> 4);
    const uint32_t b_row = (lane & 7) + (lane >> 4) * 8;
    const uint32_t b_ch  = (lane >> 3) & 1;

    #pragma unroll
    for (int s = 0; s < NST - 1; s++)
        if (s < nact)
            load_stage(sbase + (uint32_t)s * ST_BYTES, Af, Bh,
                       m0, n0, KT(s) * BK, ldk, tid);

    int sl = 0;
    #pragma unroll 1
    for (int i = 0; i < nact; i++) {
        int rem = nact - i - 1;
        if (rem >= NST - 2)  cp_wait<NST - 2>();
        else if (rem == 1)   cp_wait<1>();
        else                 cp_wait<0>();
        __syncthreads();

        if (i + NST - 1 < nact) {
            int s2 = sl + NST - 1; if (s2 >= NST) s2 -= NST;
            load_stage(sbase + (uint32_t)s2 * ST_BYTES, Af, Bh,
                       m0, n0, KT(i + NST - 1) * BK, ldk, tid);
        }

        const uint32_t sb = sbase + (uint32_t)sl * ST_BYTES;
        const uint32_t sA = sb;
        const uint32_t sB = sb + A_TILE_BYTES;

        #pragma unroll
        for (int ks = 0; ks < 4; ks++) {
            uint32_t bh[4][4];
            #pragma unroll
            for (int ng = 0; ng < 4; ng++) {
                uint32_t row = wn * 64 + ng * 16 + b_row;
                ldsm4(sB + swz(row, ks * 2 + b_ch), bh[ng]);
            }
            #pragma unroll
            for (int mt = 0; mt < 4; mt++) {
                uint32_t ah[4];
                uint32_t row = wm * 64 + mt * 16 + a_row;
                ldsm4(sA + swz(row, ks * 2 + a_ch), ah);
                #pragma unroll
                for (int nt = 0; nt < 8; nt++)
                    mma16816(acc[mt][nt], ah, bh[nt >> 1] + (nt & 1) * 2);
            }
        }
        sl++; if (sl == NST) sl = 0;
    }

    // ---- epilogue ----
    float asum = 0.0f;
    const int lrow = lane >> 2;
    const int lcol = (lane & 3) * 2;
    #pragma unroll
    for (int mt = 0; mt < 4; mt++) {
        #pragma unroll
        for (int half = 0; half < 2; half++) {
            const int m = m0 + wm * 64 + mt * 16 + lrow + half * 8;
            #pragma unroll
            for (int nt = 0; nt < 8; nt++) {
                const int n = n0 + wn * 64 + nt * 8 + lcol;
                float v0 = acc[mt][nt][half * 2 + 0] + (bias ? __ldg(bias + n) : 0.0f);
                float v1 = acc[mt][nt][half * 2 + 1] + (bias ? __ldg(bias + n + 1) : 0.0f);
                if (do_tanh) { v0 = tanhf(v0); v1 = tanhf(v1); }
                asum += fabsf(v0) + fabsf(v1);
                if (hist) {
                    int a = n >> 11, nn = n & 2047;
                    *(float2*)(hist + ((size_t)a * BATCH + m) * AREA_N + nn) =
                        make_float2(v0, v1);
                }
                if (logits)
                    *(float2*)(logits + (size_t)m * logitsN + n) = make_float2(v0, v1);
                if (Zfo)
                    *(uint32_t*)(Zfo + (size_t)m * NTOT + n) =
                        pack2h(__float2half_rn(v0), __float2half_rn(v1));
            }
        }
    }

    if (tsum) {
        #pragma unroll
        for (int o = 16; o; o >>= 1) asum += __shfl_xor_sync(0xffffffffu, asum, o);
        if (lane == 0) s_wsum[wid] = asum;
        __syncthreads();
        if (tid == 0) {
            float s = ((s_wsum[0] + s_wsum[1]) + (s_wsum[2] + s_wsum[3]))
                    + ((s_wsum[4] + s_wsum[5]) + (s_wsum[6] + s_wsum[7]));
            tsum[blockIdx.y * 64 + blockIdx.x] = s;
        }
    }
}

// ------------------------- launch -------------------------
extern "C" void kernel_launch(void* const* d_in, const int* in_sizes, int n_in,
                              void* d_out, int out_size) {
    const float* x    = (const float*)d_in[0];
    const float* Rw   = (const float*)d_in[1];
    const float* rb   = (const float*)d_in[2];
    const float* Wb   = (const float*)d_in[3];
    const float* bb   = (const float*)d_in[4];
    const float* mask = (const float*)d_in[5];
    const float* Ow   = (const float*)d_in[6];
    const float* Ob   = (const float*)d_in[7];
    const int*   aidx = (const int*)d_in[8];

    float* out  = (float*)d_out;
    float* hist = out + LOGITS_ELEMS;

    __half *whi, *rhi, *ohi, *xf, *zf[2];
    float *tsum, *gatev, *biasv, *part;
    cudaGetSymbolAddress((void**)&whi, g_Whi);
    cudaGetSymbolAddress((void**)&rhi, g_Rhi);
    cudaGetSymbolAddress((void**)&ohi, g_Ohi);
    cudaGetSymbolAddress((void**)&xf,  g_xf);
    cudaGetSymbolAddress((void**)&zf[0], g_Zf0);
    cudaGetSymbolAddress((void**)&zf[1], g_Zf1);
    cudaGetSymbolAddress((void**)&tsum,  g_tsum);
    cudaGetSymbolAddress((void**)&gatev, g_gatev);
    cudaGetSymbolAddress((void**)&biasv, g_biasv);
    cudaGetSymbolAddress((void**)&part,  g_part);

    cudaFuncSetAttribute(god_gemm, cudaFuncAttributeMaxDynamicSharedMemorySize, SMEM_DYN);

    // prep (streaming, grid-stride)
    prep_xf<<<1024, 256>>>(x);
    prep_rhalf<<<2048, 256>>>((const float4*)Rw);
    prep_ohalf<<<16384, 256>>>(Ow, aidx);

    // encode (K=1024): Z0 = tanh(x @ Rw^T + rb)
    god_gemm<<<dim3(64, 2), 256, SMEM_DYN>>>(
        xf, rhi, D_INPUT, D_INPUT / BK,
        nullptr, rb, hist, nullptr, 0, 0,
        zf[0], tsum, 1);

    // W prep (needed before tick 1)
    prep_wsplit<<<4096, 256>>>((const float4*)Wb, (const float4*)mask);

    // ticks (K=8192, area-gated)
    int p = 0;
    for (int t = 0; t < NTICKS; t++) {
        gate_bias_kernel<<<1, 256>>>(bb);
        god_gemm<<<dim3(64, 2), 256, SMEM_DYN>>>(
            zf[p], whi, NTOT, 0,
            gatev, biasv, hist + (size_t)(t + 1) * HIST_STEP, nullptr, 0, 0,
            zf[1 - p], tsum, 1);
        p ^= 1;
    }

    // logits: one 3D launch, 8-way split-K, then reduce (+Ob)
    god_gemm<<<dim3(8, 2, LOG_SPLIT), 256, SMEM_DYN>>>(
        zf[p], ohi, NTOT, LOG_KTILES,
        nullptr, nullptr, nullptr, part, NCLS, (size_t)LOGITS_ELEMS,
        nullptr, nullptr, 0);
    logits_reduce<<<LOGITS_ELEMS / 1024, 256>>>(Ob, out);
}

// round 11
// speedup vs baseline: 8.2650x; 1.0350x over previous
#include <cuda_runtime.h>
#include <cuda_fp16.h>
#include <math.h>
#include <stdint.h>

// ---------------------------------------------------------------------------
// GodAreaModel via mma.sync fp16, single-term (C = A*Bh).
// R9: 4-warp CTAs (BM=128), 2 CTAs/SM, gates+bias fused into GEMM.
// ---------------------------------------------------------------------------

#define A_NUM   4
#define AREA_N  2048
#define NTOT    8192
#define D_INPUT 1024
#define NCLS    1024
#define BATCH   512
#define NTICKS  4
#define THRESH  0.05f
#define LOGITS_ELEMS (BATCH * NCLS)
#define HIST_STEP    (A_NUM * BATCH * AREA_N)

// Block tile
#define BM 128
#define BN 128
#define BK 64
#define A_TILE_BYTES (BM * BK * 2)          // 16384
#define B_TILE_BYTES (BN * BK * 2)          // 16384
#define ST_BYTES (A_TILE_BYTES + B_TILE_BYTES)  // 32768
#define NST 3
#define SMEM_DYN (NST * ST_BYTES)           // 98304 -> 2 CTAs/SM

#define LOG_SPLIT 8
#define LOG_KTILES (NTOT / BK / LOG_SPLIT)  // 16

// ------------------------- device scratch -------------------------
__device__ __align__(256) __half g_Whi[(size_t)NTOT * NTOT];
__device__ __align__(256) __half g_Rhi[(size_t)NTOT * D_INPUT];
__device__ __align__(256) __half g_Ohi[(size_t)NCLS * NTOT];
__device__ __align__(256) __half g_xf [(size_t)BATCH * D_INPUT];
__device__ __align__(256) __half g_Zf0[(size_t)BATCH * NTOT];
__device__ __align__(256) __half g_Zf1[(size_t)BATCH * NTOT];
__device__ __align__(256) float g_part[(size_t)LOG_SPLIT * LOGITS_ELEMS];
__device__ __align__(256) float g_tsA[256];
__device__ __align__(256) float g_tsB[256];

// ------------------------- helpers -------------------------
__device__ __forceinline__ uint32_t smem_u32(const void* p) {
    return (uint32_t)__cvta_generic_to_shared(p);
}
__device__ __forceinline__ uint32_t pack2h(__half a, __half b) {
    __half2 v; v.x = a; v.y = b;
    return *reinterpret_cast<uint32_t*>(&v);
}
__device__ __forceinline__ void cp16(uint32_t saddr, const void* g) {
    asm volatile("cp.async.cg.shared.global [%0], [%1], 16;" :: "r"(saddr), "l"(g));
}
template<int N>
__device__ __forceinline__ void cp_wait() {
    asm volatile("cp.async.wait_group %0;" :: "n"(N) : "memory");
}
__device__ __forceinline__ uint32_t swz(uint32_t row, uint32_t chunk) {
    return row * 128u + ((chunk ^ (row & 7u)) << 4);
}
__device__ __forceinline__ void ldsm4(uint32_t addr, uint32_t* r) {
    asm volatile("ldmatrix.sync.aligned.m8n8.x4.shared.b16 {%0,%1,%2,%3}, [%4];"
                 : "=r"(r[0]), "=r"(r[1]), "=r"(r[2]), "=r"(r[3]) : "r"(addr));
}
__device__ __forceinline__ void mma16816(float* c, const uint32_t* a, const uint32_t* b) {
    asm volatile(
        "mma.sync.aligned.m16n8k16.row.col.f32.f16.f16.f32 "
        "{%0,%1,%2,%3}, {%4,%5,%6,%7}, {%8,%9}, {%0,%1,%2,%3};"
        : "+f"(c[0]), "+f"(c[1]), "+f"(c[2]), "+f"(c[3])
        : "r"(a[0]), "r"(a[1]), "r"(a[2]), "r"(a[3]), "r"(b[0]), "r"(b[1]));
}

// ------------------------- prep kernels -------------------------
__global__ void prep_wsplit(const float4* __restrict__ W, const float4* __restrict__ mask) {
    const size_t total = (size_t)NTOT * NTOT / 4;
    const size_t stride = (size_t)gridDim.x * blockDim.x;
    for (size_t q = (size_t)blockIdx.x * blockDim.x + threadIdx.x; q < total; q += stride) {
        float4 w  = W[q];
        float4 mk = mask[q];
        float v0 = w.x * fminf(fmaxf(mk.x, 0.f), 1.f);
        float v1 = w.y * fminf(fmaxf(mk.y, 0.f), 1.f);
        float v2 = w.z * fminf(fmaxf(mk.z, 0.f), 1.f);
        float v3 = w.w * fminf(fmaxf(mk.w, 0.f), 1.f);
        size_t s = q * 4;
        int m = (int)(s & 2047);
        size_t r = s >> 11;
        int n = (int)(r & 2047); r >>= 11;
        int i = (int)(r & 3);
        int o = (int)(r >> 2);
        size_t dst = ((size_t)((o << 11) | n)) * NTOT + ((i << 11) | m);
        uint2 out;
        out.x = pack2h(__float2half_rn(v0), __float2half_rn(v1));
        out.y = pack2h(__float2half_rn(v2), __float2half_rn(v3));
        *(uint2*)(g_Whi + dst) = out;
    }
}
__global__ void prep_rhalf(const float4* __restrict__ Rw) {
    const size_t total = (size_t)NTOT * D_INPUT / 4;
    const size_t stride = (size_t)gridDim.x * blockDim.x;
    for (size_t q = (size_t)blockIdx.x * blockDim.x + threadIdx.x; q < total; q += stride) {
        float4 w = Rw[q];
        uint2 out;
        out.x = pack2h(__float2half_rn(w.x), __float2half_rn(w.y));
        out.y = pack2h(__float2half_rn(w.z), __float2half_rn(w.w));
        *(uint2*)(g_Rhi + q * 4) = out;
    }
}
__global__ void prep_ohalf(const float* __restrict__ Ow, const int* __restrict__ aidx) {
    size_t s = ((size_t)blockIdx.x * blockDim.x + threadIdx.x) * 2;
    int k = (int)(s & 8191);
    int c = (int)(s >> 13);
    float w0 = Ow[(size_t)c * NTOT + aidx[k]];
    float w1 = Ow[(size_t)c * NTOT + aidx[k + 1]];
    *(uint32_t*)(g_Ohi + s) = pack2h(__float2half_rn(w0), __float2half_rn(w1));
}
__global__ void prep_xf(const float* __restrict__ x) {
    size_t s = ((size_t)blockIdx.x * blockDim.x + threadIdx.x) * 2;
    float2 w = *(const float2*)(x + s);
    *(uint32_t*)(g_xf + s) = pack2h(__float2half_rn(w.x), __float2half_rn(w.y));
}
__global__ void logits_reduce(const float* __restrict__ Ob, float* __restrict__ out) {
    int i = (blockIdx.x * 256 + threadIdx.x) * 4;
    float4 a = *(const float4*)(g_part + i);
    #pragma unroll
    for (int s = 1; s < LOG_SPLIT; s++) {
        float4 b = *(const float4*)(g_part + (size_t)s * LOGITS_ELEMS + i);
        a.x += b.x; a.y += b.y; a.z += b.z; a.w += b.w;
    }
    int n = i & (NCLS - 1);
    float4 ob = *(const float4*)(Ob + n);
    a.x += ob.x; a.y += ob.y; a.z += ob.z; a.w += ob.w;
    *(float4*)(out + i) = a;
}

// ------------------------- stage loader (128 threads) -------------------------
__device__ __forceinline__ void load_tile128(uint32_t sb, const __half* g, int ld, int tid) {
    #pragma unroll
    for (int r = 0; r < 8; r++) {
        int id = tid + r * 128;
        uint32_t row = (uint32_t)id >> 3, c = (uint32_t)id & 7;
        cp16(sb + swz(row, c), g + (size_t)row * ld + c * 8);
    }
}
__device__ __forceinline__ void load_stage(
    uint32_t sb, const __half* Af, const __half* Bh,
    int m0, int n0, int k0, int ld, int tid)
{
    load_tile128(sb,                Af + (size_t)m0 * ld + k0, ld, tid);
    load_tile128(sb + A_TILE_BYTES, Bh + (size_t)n0 * ld + k0, ld, tid);
    asm volatile("cp.async.commit_group;" ::: "memory");
}

// ------------------------- main GEMM -------------------------
// grid (N/BN, M/BM, zsplit). 4 warps: 2(m) x 2(n), warp tile 64x64.
// use_gate: gates computed from tsum_in in prologue; gated bias from bb4 in epilogue.
__global__ __launch_bounds__(128, 2)
void god_gemm(const __half* __restrict__ Af, const __half* __restrict__ Bh,
              int ldk, int ktiles_in,
              int use_gate,
              const float* __restrict__ tsum_in,
              const float* __restrict__ bias,
              const float* __restrict__ bb4,
              float* __restrict__ hist,
              float* __restrict__ logits, int logitsN, size_t zstride,
              __half* __restrict__ Zfo,
              float* __restrict__ tsum_out,
              int do_tanh)
{
    extern __shared__ char dsm[];
    __shared__ float s_gate[A_NUM];
    __shared__ float s_wsum[4];

    const int tid  = threadIdx.x;
    const int wid  = tid >> 5, lane = tid & 31;
    const int wm   = wid >> 1;          // 0..1
    const int wn   = wid & 1;           // 0..1
    const int m0   = blockIdx.y * BM;
    const int n0   = blockIdx.x * BN;
    const int k0tile = blockIdx.z * ktiles_in;
    const uint32_t sbase = smem_u32(dsm);
    if (logits) logits += (size_t)blockIdx.z * zstride;

    // gates from previous kernel's tilesums (deterministic, fixed order)
    if (tid < A_NUM) {
        float g = 1.0f;
        if (use_gate) {
            float s = 0.0f;
            #pragma unroll
            for (int y = 0; y < 4; y++)
                for (int xx = 0; xx < 16; xx++)
                    s += __ldg(tsum_in + y * 64 + tid * 16 + xx);
            g = (s * (1.0f / (float)(BATCH * AREA_N)) > THRESH) ? 1.0f : 0.0f;
        }
        s_gate[tid] = g;
    }
    __syncthreads();

    int aa[A_NUM];
    int nact;
    if (use_gate) {
        int c = 0;
        #pragma unroll
        for (int a = 0; a < A_NUM; a++)
            if (s_gate[a] != 0.0f) aa[c++] = a;
        nact = c * 32;                 // 32 BK-tiles per area
    } else {
        nact = ktiles_in;
        aa[0] = 0;
    }
    #define KT(i) (use_gate ? (aa[(i) >> 5] * 32 + ((i) & 31)) : (k0tile + (i)))

    float acc[4][8][4];
    #pragma unroll
    for (int a = 0; a < 4; a++)
        #pragma unroll
        for (int b = 0; b < 8; b++)
            #pragma unroll
            for (int c = 0; c < 4; c++) acc[a][b][c] = 0.0f;

    const uint32_t a_row = (lane & 7) + ((lane >> 3) & 1) * 8;
    const uint32_t a_ch  = (lane >> 4);
    const uint32_t b_row = (lane & 7) + (lane >> 4) * 8;
    const uint32_t b_ch  = (lane >> 3) & 1;

    #pragma unroll
    for (int s = 0; s < NST - 1; s++)
        if (s < nact)
            load_stage(sbase + (uint32_t)s * ST_BYTES, Af, Bh,
                       m0, n0, KT(s) * BK, ldk, tid);

    int sl = 0;
    #pragma unroll 1
    for (int i = 0; i < nact; i++) {
        if (nact - i - 1 >= NST - 2) cp_wait<NST - 2>();
        else                         cp_wait<0>();
        __syncthreads();

        if (i + NST - 1 < nact) {
            int s2 = sl + NST - 1; if (s2 >= NST) s2 -= NST;
            load_stage(sbase + (uint32_t)s2 * ST_BYTES, Af, Bh,
                       m0, n0, KT(i + NST - 1) * BK, ldk, tid);
        }

        const uint32_t sb = sbase + (uint32_t)sl * ST_BYTES;
        const uint32_t sA = sb;
        const uint32_t sB = sb + A_TILE_BYTES;

        #pragma unroll
        for (int ks = 0; ks < 4; ks++) {
            uint32_t bh[4][4];
            #pragma unroll
            for (int ng = 0; ng < 4; ng++) {
                uint32_t row = wn * 64 + ng * 16 + b_row;
                ldsm4(sB + swz(row, ks * 2 + b_ch), bh[ng]);
            }
            #pragma unroll
            for (int mt = 0; mt < 4; mt++) {
                uint32_t ah[4];
                uint32_t row = wm * 64 + mt * 16 + a_row;
                ldsm4(sA + swz(row, ks * 2 + a_ch), ah);
                #pragma unroll
                for (int nt = 0; nt < 8; nt++)
                    mma16816(acc[mt][nt], ah, bh[nt >> 1] + (nt & 1) * 2);
            }
        }
        sl++; if (sl == NST) sl = 0;
    }

    // ---- epilogue: (gated) bias + tanh + hist/logits/Z + |Z| partial ----
    float asum = 0.0f;
    const int lrow = lane >> 2;
    const int lcol = (lane & 3) * 2;
    #pragma unroll
    for (int mt = 0; mt < 4; mt++) {
        #pragma unroll
        for (int half = 0; half < 2; half++) {
            const int m = m0 + wm * 64 + mt * 16 + lrow + half * 8;
            #pragma unroll
            for (int nt = 0; nt < 8; nt++) {
                const int n = n0 + wn * 64 + nt * 8 + lcol;
                float b0 = 0.0f, b1 = 0.0f;
                if (bb4) {
                    int o = n >> 11, nn = n & 2047;
                    #pragma unroll
                    for (int ia = 0; ia < A_NUM; ia++) {
                        const float* row = bb4 + (size_t)(o * A_NUM + ia) * AREA_N + nn;
                        b0 += s_gate[ia] * __ldg(row);
                        b1 += s_gate[ia] * __ldg(row + 1);
                    }
                } else if (bias) {
                    b0 = __ldg(bias + n);
                    b1 = __ldg(bias + n + 1);
                }
                float v0 = acc[mt][nt][half * 2 + 0] + b0;
                float v1 = acc[mt][nt][half * 2 + 1] + b1;
                if (do_tanh) { v0 = tanhf(v0); v1 = tanhf(v1); }
                asum += fabsf(v0) + fabsf(v1);
                if (hist) {
                    int a = n >> 11, nn = n & 2047;
                    *(float2*)(hist + ((size_t)a * BATCH + m) * AREA_N + nn) =
                        make_float2(v0, v1);
                }
                if (logits)
                    *(float2*)(logits + (size_t)m * logitsN + n) = make_float2(v0, v1);
                if (Zfo)
                    *(uint32_t*)(Zfo + (size_t)m * NTOT + n) =
                        pack2h(__float2half_rn(v0), __float2half_rn(v1));
            }
        }
    }

    if (tsum_out) {
        #pragma unroll
        for (int o = 16; o; o >>= 1) asum += __shfl_xor_sync(0xffffffffu, asum, o);
        if (lane == 0) s_wsum[wid] = asum;
        __syncthreads();
        if (tid == 0)
            tsum_out[blockIdx.y * 64 + blockIdx.x] =
                (s_wsum[0] + s_wsum[1]) + (s_wsum[2] + s_wsum[3]);
    }
}

// ------------------------- launch -------------------------
extern "C" void kernel_launch(void* const* d_in, const int* in_sizes, int n_in,
                              void* d_out, int out_size) {
    const float* x    = (const float*)d_in[0];
    const float* Rw   = (const float*)d_in[1];
    const float* rb   = (const float*)d_in[2];
    const float* Wb   = (const float*)d_in[3];
    const float* bb   = (const float*)d_in[4];
    const float* mask = (const float*)d_in[5];
    const float* Ow   = (const float*)d_in[6];
    const float* Ob   = (const float*)d_in[7];
    const int*   aidx = (const int*)d_in[8];

    float* out  = (float*)d_out;
    float* hist = out + LOGITS_ELEMS;

    __half *whi, *rhi, *ohi, *xf, *zf[2];
    float *ts[2], *part;
    cudaGetSymbolAddress((void**)&whi, g_Whi);
    cudaGetSymbolAddress((void**)&rhi, g_Rhi);
    cudaGetSymbolAddress((void**)&ohi, g_Ohi);
    cudaGetSymbolAddress((void**)&xf,  g_xf);
    cudaGetSymbolAddress((void**)&zf[0], g_Zf0);
    cudaGetSymbolAddress((void**)&zf[1], g_Zf1);
    cudaGetSymbolAddress((void**)&ts[0], g_tsA);
    cudaGetSymbolAddress((void**)&ts[1], g_tsB);
    cudaGetSymbolAddress((void**)&part,  g_part);

    cudaFuncSetAttribute(god_gemm, cudaFuncAttributeMaxDynamicSharedMemorySize, SMEM_DYN);

    // prep
    prep_xf<<<1024, 256>>>(x);
    prep_rhalf<<<2048, 256>>>((const float4*)Rw);
    prep_ohalf<<<16384, 256>>>(Ow, aidx);

    // encode (K=1024): Z0 = tanh(x @ Rw^T + rb); writes hist[0], Z0, tsum[0]
    god_gemm<<<dim3(64, 4), 128, SMEM_DYN>>>(
        xf, rhi, D_INPUT, D_INPUT / BK,
        0, nullptr, rb, nullptr,
        hist, nullptr, 0, 0,
        zf[0], ts[0], 1);

    // W prep (needed before tick 1)
    prep_wsplit<<<4096, 256>>>((const float4*)Wb, (const float4*)mask);

    // ticks (K=8192, area-gated; gates+bias fused; tsum ping-pong)
    int p = 0;
    for (int t = 0; t < NTICKS; t++) {
        god_gemm<<<dim3(64, 4), 128, SMEM_DYN>>>(
            zf[p], whi, NTOT, 0,
            1, ts[t & 1], nullptr, bb,
            hist + (size_t)(t + 1) * HIST_STEP, nullptr, 0, 0,
            zf[1 - p], ts[(t & 1) ^ 1], 1);
        p ^= 1;
    }

    // logits: one 3D launch, 8-way split-K, then reduce (+Ob)
    god_gemm<<<dim3(8, 4, LOG_SPLIT), 128, SMEM_DYN>>>(
        zf[p], ohi, NTOT, LOG_KTILES,
        0, nullptr, nullptr, nullptr,
        nullptr, part, NCLS, (size_t)LOGITS_ELEMS,
        nullptr, nullptr, 0);
    logits_reduce<<<LOGITS_ELEMS / 1024, 256>>>(Ob, out);
}

// round 13
// speedup vs baseline: 8.3327x; 1.0082x over previous
#include <cuda_runtime.h>
#include <cuda_fp16.h>
#include <math.h>
#include <stdint.h>

// ---------------------------------------------------------------------------
// GodAreaModel via mma.sync fp16, single-term (C = A*Bh).
// R10: register-level double-buffered fragments (ldsm ks+1 overlaps MMA ks).
// ---------------------------------------------------------------------------

#define A_NUM   4
#define AREA_N  2048
#define NTOT    8192
#define D_INPUT 1024
#define NCLS    1024
#define BATCH   512
#define NTICKS  4
#define THRESH  0.05f
#define LOGITS_ELEMS (BATCH * NCLS)
#define HIST_STEP    (A_NUM * BATCH * AREA_N)

// Block tile
#define BM 128
#define BN 128
#define BK 64
#define A_TILE_BYTES (BM * BK * 2)          // 16384
#define B_TILE_BYTES (BN * BK * 2)          // 16384
#define ST_BYTES (A_TILE_BYTES + B_TILE_BYTES)  // 32768
#define NST 3
#define SMEM_DYN (NST * ST_BYTES)           // 98304 -> 2 CTAs/SM

#define LOG_SPLIT 8
#define LOG_KTILES (NTOT / BK / LOG_SPLIT)  // 16

// ------------------------- device scratch -------------------------
__device__ __align__(256) __half g_Whi[(size_t)NTOT * NTOT];
__device__ __align__(256) __half g_Rhi[(size_t)NTOT * D_INPUT];
__device__ __align__(256) __half g_Ohi[(size_t)NCLS * NTOT];
__device__ __align__(256) __half g_xf [(size_t)BATCH * D_INPUT];
__device__ __align__(256) __half g_Zf0[(size_t)BATCH * NTOT];
__device__ __align__(256) __half g_Zf1[(size_t)BATCH * NTOT];
__device__ __align__(256) float g_part[(size_t)LOG_SPLIT * LOGITS_ELEMS];
__device__ __align__(256) float g_tsA[256];
__device__ __align__(256) float g_tsB[256];

// ------------------------- helpers -------------------------
__device__ __forceinline__ uint32_t smem_u32(const void* p) {
    return (uint32_t)__cvta_generic_to_shared(p);
}
__device__ __forceinline__ uint32_t pack2h(__half a, __half b) {
    __half2 v; v.x = a; v.y = b;
    return *reinterpret_cast<uint32_t*>(&v);
}
__device__ __forceinline__ void cp16(uint32_t saddr, const void* g) {
    asm volatile("cp.async.cg.shared.global [%0], [%1], 16;" :: "r"(saddr), "l"(g));
}
template<int N>
__device__ __forceinline__ void cp_wait() {
    asm volatile("cp.async.wait_group %0;" :: "n"(N) : "memory");
}
__device__ __forceinline__ uint32_t swz(uint32_t row, uint32_t chunk) {
    return row * 128u + ((chunk ^ (row & 7u)) << 4);
}
__device__ __forceinline__ void ldsm4(uint32_t addr, uint32_t* r) {
    asm volatile("ldmatrix.sync.aligned.m8n8.x4.shared.b16 {%0,%1,%2,%3}, [%4];"
                 : "=r"(r[0]), "=r"(r[1]), "=r"(r[2]), "=r"(r[3]) : "r"(addr));
}
__device__ __forceinline__ void mma16816(float* c, const uint32_t* a, const uint32_t* b) {
    asm volatile(
        "mma.sync.aligned.m16n8k16.row.col.f32.f16.f16.f32 "
        "{%0,%1,%2,%3}, {%4,%5,%6,%7}, {%8,%9}, {%0,%1,%2,%3};"
        : "+f"(c[0]), "+f"(c[1]), "+f"(c[2]), "+f"(c[3])
        : "r"(a[0]), "r"(a[1]), "r"(a[2]), "r"(a[3]), "r"(b[0]), "r"(b[1]));
}

// ------------------------- prep kernels -------------------------
__global__ void prep_wsplit(const float4* __restrict__ W, const float4* __restrict__ mask) {
    const size_t total = (size_t)NTOT * NTOT / 4;
    const size_t stride = (size_t)gridDim.x * blockDim.x;
    for (size_t q = (size_t)blockIdx.x * blockDim.x + threadIdx.x; q < total; q += stride) {
        float4 w  = W[q];
        float4 mk = mask[q];
        float v0 = w.x * fminf(fmaxf(mk.x, 0.f), 1.f);
        float v1 = w.y * fminf(fmaxf(mk.y, 0.f), 1.f);
        float v2 = w.z * fminf(fmaxf(mk.z, 0.f), 1.f);
        float v3 = w.w * fminf(fmaxf(mk.w, 0.f), 1.f);
        size_t s = q * 4;
        int m = (int)(s & 2047);
        size_t r = s >> 11;
        int n = (int)(r & 2047); r >>= 11;
        int i = (int)(r & 3);
        int o = (int)(r >> 2);
        size_t dst = ((size_t)((o << 11) | n)) * NTOT + ((i << 11) | m);
        uint2 out;
        out.x = pack2h(__float2half_rn(v0), __float2half_rn(v1));
        out.y = pack2h(__float2half_rn(v2), __float2half_rn(v3));
        *(uint2*)(g_Whi + dst) = out;
    }
}
__global__ void prep_rhalf(const float4* __restrict__ Rw) {
    const size_t total = (size_t)NTOT * D_INPUT / 4;
    const size_t stride = (size_t)gridDim.x * blockDim.x;
    for (size_t q = (size_t)blockIdx.x * blockDim.x + threadIdx.x; q < total; q += stride) {
        float4 w = Rw[q];
        uint2 out;
        out.x = pack2h(__float2half_rn(w.x), __float2half_rn(w.y));
        out.y = pack2h(__float2half_rn(w.z), __float2half_rn(w.w));
        *(uint2*)(g_Rhi + q * 4) = out;
    }
}
__global__ void prep_ohalf(const float* __restrict__ Ow, const int* __restrict__ aidx) {
    size_t s = ((size_t)blockIdx.x * blockDim.x + threadIdx.x) * 2;
    int k = (int)(s & 8191);
    int c = (int)(s >> 13);
    float w0 = Ow[(size_t)c * NTOT + aidx[k]];
    float w1 = Ow[(size_t)c * NTOT + aidx[k + 1]];
    *(uint32_t*)(g_Ohi + s) = pack2h(__float2half_rn(w0), __float2half_rn(w1));
}
__global__ void prep_xf(const float* __restrict__ x) {
    size_t s = ((size_t)blockIdx.x * blockDim.x + threadIdx.x) * 2;
    float2 w = *(const float2*)(x + s);
    *(uint32_t*)(g_xf + s) = pack2h(__float2half_rn(w.x), __float2half_rn(w.y));
}
__global__ void logits_reduce(const float* __restrict__ Ob, float* __restrict__ out) {
    int i = (blockIdx.x * 256 + threadIdx.x) * 4;
    float4 a = *(const float4*)(g_part + i);
    #pragma unroll
    for (int s = 1; s < LOG_SPLIT; s++) {
        float4 b = *(const float4*)(g_part + (size_t)s * LOGITS_ELEMS + i);
        a.x += b.x; a.y += b.y; a.z += b.z; a.w += b.w;
    }
    int n = i & (NCLS - 1);
    float4 ob = *(const float4*)(Ob + n);
    a.x += ob.x; a.y += ob.y; a.z += ob.z; a.w += ob.w;
    *(float4*)(out + i) = a;
}

// ------------------------- stage loader (128 threads) -------------------------
__device__ __forceinline__ void load_tile128(uint32_t sb, const __half* g, int ld, int tid) {
    #pragma unroll
    for (int r = 0; r < 8; r++) {
        int id = tid + r * 128;
        uint32_t row = (uint32_t)id >> 3, c = (uint32_t)id & 7;
        cp16(sb + swz(row, c), g + (size_t)row * ld + c * 8);
    }
}
__device__ __forceinline__ void load_stage(
    uint32_t sb, const __half* Af, const __half* Bh,
    int m0, int n0, int k0, int ld, int tid)
{
    load_tile128(sb,                Af + (size_t)m0 * ld + k0, ld, tid);
    load_tile128(sb + A_TILE_BYTES, Bh + (size_t)n0 * ld + k0, ld, tid);
    asm volatile("cp.async.commit_group;" ::: "memory");
}

// ------------------------- main GEMM -------------------------
// grid (N/BN, M/BM, zsplit). 4 warps: 2(m) x 2(n), warp tile 64x64.
// Fragments double-buffered in registers: ldsm(ks+1) overlaps MMA(ks).
__global__ __launch_bounds__(128, 2)
void god_gemm(const __half* __restrict__ Af, const __half* __restrict__ Bh,
              int ldk, int ktiles_in,
              int use_gate,
              const float* __restrict__ tsum_in,
              const float* __restrict__ bias,
              const float* __restrict__ bb4,
              float* __restrict__ hist,
              float* __restrict__ logits, int logitsN, size_t zstride,
              __half* __restrict__ Zfo,
              float* __restrict__ tsum_out,
              int do_tanh)
{
    extern __shared__ char dsm[];
    __shared__ float s_gate[A_NUM];
    __shared__ float s_wsum[4];

    const int tid  = threadIdx.x;
    const int wid  = tid >> 5, lane = tid & 31;
    const int wm   = wid >> 1;
    const int wn   = wid & 1;
    const int m0   = blockIdx.y * BM;
    const int n0   = blockIdx.x * BN;
    const int k0tile = blockIdx.z * ktiles_in;
    const uint32_t sbase = smem_u32(dsm);
    if (logits) logits += (size_t)blockIdx.z * zstride;

    // gates from previous kernel's tilesums (deterministic, fixed order)
    if (tid < A_NUM) {
        float g = 1.0f;
        if (use_gate) {
            float s = 0.0f;
            #pragma unroll
            for (int y = 0; y < 4; y++)
                for (int xx = 0; xx < 16; xx++)
                    s += __ldg(tsum_in + y * 64 + tid * 16 + xx);
            g = (s * (1.0f / (float)(BATCH * AREA_N)) > THRESH) ? 1.0f : 0.0f;
        }
        s_gate[tid] = g;
    }
    __syncthreads();

    int aa[A_NUM];
    int nact;
    if (use_gate) {
        int c = 0;
        #pragma unroll
        for (int a = 0; a < A_NUM; a++)
            if (s_gate[a] != 0.0f) aa[c++] = a;
        nact = c * 32;
    } else {
        nact = ktiles_in;
        aa[0] = 0;
    }
    #define KT(i) (use_gate ? (aa[(i) >> 5] * 32 + ((i) & 31)) : (k0tile + (i)))

    float acc[4][8][4];
    #pragma unroll
    for (int a = 0; a < 4; a++)
        #pragma unroll
        for (int b = 0; b < 8; b++)
            #pragma unroll
            for (int c = 0; c < 4; c++) acc[a][b][c] = 0.0f;

    const uint32_t a_row = (lane & 7) + ((lane >> 3) & 1) * 8;
    const uint32_t a_ch  = (lane >> 4);
    const uint32_t b_row = (lane & 7) + (lane >> 4) * 8;
    const uint32_t b_ch  = (lane >> 3) & 1;
    const uint32_t arow_s = wm * 64 + a_row;   // row within A tile (+mt*16)
    const uint32_t brow_s = wn * 64 + b_row;   // row within B tile (+ng*16)

    #pragma unroll
    for (int s = 0; s < NST - 1; s++)
        if (s < nact)
            load_stage(sbase + (uint32_t)s * ST_BYTES, Af, Bh,
                       m0, n0, KT(s) * BK, ldk, tid);

    uint32_t ah[2][4][4], bh[2][4][4];

    int sl = 0;
    #pragma unroll 1
    for (int i = 0; i < nact; i++) {
        if (nact - i - 1 >= NST - 2) cp_wait<NST - 2>();
        else                         cp_wait<0>();
        __syncthreads();

        if (i + NST - 1 < nact) {
            int s2 = sl + NST - 1; if (s2 >= NST) s2 -= NST;
            load_stage(sbase + (uint32_t)s2 * ST_BYTES, Af, Bh,
                       m0, n0, KT(i + NST - 1) * BK, ldk, tid);
        }

        const uint32_t sA = sbase + (uint32_t)sl * ST_BYTES;
        const uint32_t sB = sA + A_TILE_BYTES;

        // prime fragments for ks=0
        #pragma unroll
        for (int ng = 0; ng < 4; ng++)
            ldsm4(sB + swz(brow_s + ng * 16, b_ch), bh[0][ng]);
        #pragma unroll
        for (int mt = 0; mt < 4; mt++)
            ldsm4(sA + swz(arow_s + mt * 16, a_ch), ah[0][mt]);

        #pragma unroll
        for (int ks = 0; ks < 4; ks++) {
            const int cur = ks & 1, nxt = cur ^ 1;
            if (ks < 3) {   // prefetch fragments for ks+1 while computing ks
                #pragma unroll
                for (int ng = 0; ng < 4; ng++)
                    ldsm4(sB + swz(brow_s + ng * 16, (ks + 1) * 2 + b_ch), bh[nxt][ng]);
                #pragma unroll
                for (int mt = 0; mt < 4; mt++)
                    ldsm4(sA + swz(arow_s + mt * 16, (ks + 1) * 2 + a_ch), ah[nxt][mt]);
            }
            #pragma unroll
            for (int mt = 0; mt < 4; mt++)
                #pragma unroll
                for (int nt = 0; nt < 8; nt++)
                    mma16816(acc[mt][nt], ah[cur][mt], bh[cur][nt >> 1] + (nt & 1) * 2);
        }
        sl++; if (sl == NST) sl = 0;
    }

    // ---- epilogue: (gated) bias + tanh + hist/logits/Z + |Z| partial ----
    float asum = 0.0f;
    const int lrow = lane >> 2;
    const int lcol = (lane & 3) * 2;
    #pragma unroll
    for (int mt = 0; mt < 4; mt++) {
        #pragma unroll
        for (int half = 0; half < 2; half++) {
            const int m = m0 + wm * 64 + mt * 16 + lrow + half * 8;
            #pragma unroll
            for (int nt = 0; nt < 8; nt++) {
                const int n = n0 + wn * 64 + nt * 8 + lcol;
                float b0 = 0.0f, b1 = 0.0f;
                if (bb4) {
                    int o = n >> 11, nn = n & 2047;
                    #pragma unroll
                    for (int ia = 0; ia < A_NUM; ia++) {
                        const float* row = bb4 + (size_t)(o * A_NUM + ia) * AREA_N + nn;
                        b0 += s_gate[ia] * __ldg(row);
                        b1 += s_gate[ia] * __ldg(row + 1);
                    }
                } else if (bias) {
                    b0 = __ldg(bias + n);
                    b1 = __ldg(bias + n + 1);
                }
                float v0 = acc[mt][nt][half * 2 + 0] + b0;
                float v1 = acc[mt][nt][half * 2 + 1] + b1;
                if (do_tanh) { v0 = tanhf(v0); v1 = tanhf(v1); }
                asum += fabsf(v0) + fabsf(v1);
                if (hist) {
                    int a = n >> 11, nn = n & 2047;
                    *(float2*)(hist + ((size_t)a * BATCH + m) * AREA_N + nn) =
                        make_float2(v0, v1);
                }
                if (logits)
                    *(float2*)(logits + (size_t)m * logitsN + n) = make_float2(v0, v1);
                if (Zfo)
                    *(uint32_t*)(Zfo + (size_t)m * NTOT + n) =
                        pack2h(__float2half_rn(v0), __float2half_rn(v1));
            }
        }
    }

    if (tsum_out) {
        #pragma unroll
        for (int o = 16; o; o >>= 1) asum += __shfl_xor_sync(0xffffffffu, asum, o);
        if (lane == 0) s_wsum[wid] = asum;
        __syncthreads();
        if (tid == 0)
            tsum_out[blockIdx.y * 64 + blockIdx.x] =
                (s_wsum[0] + s_wsum[1]) + (s_wsum[2] + s_wsum[3]);
    }
}

// ------------------------- launch -------------------------
extern "C" void kernel_launch(void* const* d_in, const int* in_sizes, int n_in,
                              void* d_out, int out_size) {
    const float* x    = (const float*)d_in[0];
    const float* Rw   = (const float*)d_in[1];
    const float* rb   = (const float*)d_in[2];
    const float* Wb   = (const float*)d_in[3];
    const float* bb   = (const float*)d_in[4];
    const float* mask = (const float*)d_in[5];
    const float* Ow   = (const float*)d_in[6];
    const float* Ob   = (const float*)d_in[7];
    const int*   aidx = (const int*)d_in[8];

    float* out  = (float*)d_out;
    float* hist = out + LOGITS_ELEMS;

    __half *whi, *rhi, *ohi, *xf, *zf[2];
    float *ts[2], *part;
    cudaGetSymbolAddress((void**)&whi, g_Whi);
    cudaGetSymbolAddress((void**)&rhi, g_Rhi);
    cudaGetSymbolAddress((void**)&ohi, g_Ohi);
    cudaGetSymbolAddress((void**)&xf,  g_xf);
    cudaGetSymbolAddress((void**)&zf[0], g_Zf0);
    cudaGetSymbolAddress((void**)&zf[1], g_Zf1);
    cudaGetSymbolAddress((void**)&ts[0], g_tsA);
    cudaGetSymbolAddress((void**)&ts[1], g_tsB);
    cudaGetSymbolAddress((void**)&part,  g_part);

    cudaFuncSetAttribute(god_gemm, cudaFuncAttributeMaxDynamicSharedMemorySize, SMEM_DYN);

    // prep
    prep_xf<<<1024, 256>>>(x);
    prep_rhalf<<<2048, 256>>>((const float4*)Rw);
    prep_ohalf<<<16384, 256>>>(Ow, aidx);

    // encode (K=1024): Z0 = tanh(x @ Rw^T + rb); writes hist[0], Z0, tsum[0]
    god_gemm<<<dim3(64, 4), 128, SMEM_DYN>>>(
        xf, rhi, D_INPUT, D_INPUT / BK,
        0, nullptr, rb, nullptr,
        hist, nullptr, 0, 0,
        zf[0], ts[0], 1);

    // W prep (needed before tick 1)
    prep_wsplit<<<4096, 256>>>((const float4*)Wb, (const float4*)mask);

    // ticks (K=8192, area-gated; gates+bias fused; tsum ping-pong)
    int p = 0;
    for (int t = 0; t < NTICKS; t++) {
        god_gemm<<<dim3(64, 4), 128, SMEM_DYN>>>(
            zf[p], whi, NTOT, 0,
            1, ts[t & 1], nullptr, bb,
            hist + (size_t)(t + 1) * HIST_STEP, nullptr, 0, 0,
            zf[1 - p], ts[(t & 1) ^ 1], 1);
        p ^= 1;
    }

    // logits: one 3D launch, 8-way split-K, then reduce (+Ob)
    god_gemm<<<dim3(8, 4, LOG_SPLIT), 128, SMEM_DYN>>>(
        zf[p], ohi, NTOT, LOG_KTILES,
        0, nullptr, nullptr, nullptr,
        nullptr, part, NCLS, (size_t)LOGITS_ELEMS,
        nullptr, nullptr, 0);
    logits_reduce<<<LOGITS_ELEMS / 1024, 256>>>(Ob, out);
}